// round 3
// baseline (speedup 1.0000x reference)
#include <cuda_runtime.h>
#include <math.h>

// ---------------- problem constants ----------------
#define SS   2048
#define BB   2
#define DD   768
#define HH   12
#define DHH  64
#define FF   3072
#define EE   8
#define TT   4096            // S*B
#define CAPN 1024            // capacity

// ---------------- device scratch (allowed: __device__ globals) ----------------
__device__ float g_qkv [(size_t)TT * 3 * DD];     // [T, 2304]
__device__ float g_ctx [(size_t)TT * DD];         // attention context [T, D]
__device__ float g_attn[(size_t)TT * DD];         // attn out-proj     [T, D]
__device__ float g_x   [(size_t)TT * DD];         // post-LN1          [T, D]
__device__ float g_buf [(size_t)EE * CAPN * DD];  // expert input buffers
__device__ float g_h   [(size_t)EE * CAPN * FF];  // expert hidden
__device__ float g_y   [(size_t)EE * CAPN * DD];  // expert output
__device__ int   g_eidx[TT];
__device__ int   g_pos [TT];
__device__ float g_gate[TT];
__device__ int   g_cnt    [EE];                   // min(count, CAP)
__device__ int   g_cntfull[EE];                   // full count (for lb loss)
__device__ float g_probsum[EE];

// ---------------- zero accumulators ----------------
__global__ void zero_kernel() {
    if (threadIdx.x < EE) g_probsum[threadIdx.x] = 0.f;
}

// ---------------- GEMM: C[M,N] = A[M,K] @ Bt[N,K]^T + bias[N] ----------------
// grid: (N/64, M/64), block 256. M,N multiples of 64, K multiple of 16.
__global__ __launch_bounds__(256) void gemm_abt(
    const float* __restrict__ A, const float* __restrict__ Bt,
    const float* __restrict__ bias, float* __restrict__ C, int N, int K)
{
    __shared__ float As[16][68];
    __shared__ float Bs[16][68];
    int tid = threadIdx.x;
    int tx = tid & 15, ty = tid >> 4;
    int m0 = blockIdx.y * 64, n0 = blockIdx.x * 64;
    int lr = tid >> 2;              // 0..63 (row within tile)
    int lk = (tid & 3) * 4;         // 0,4,8,12
    float acc[4][4];
    #pragma unroll
    for (int i = 0; i < 4; i++)
        #pragma unroll
        for (int j = 0; j < 4; j++) acc[i][j] = 0.f;

    for (int k0 = 0; k0 < K; k0 += 16) {
        float4 a4 = *(const float4*)(A  + (size_t)(m0 + lr) * K + k0 + lk);
        float4 b4 = *(const float4*)(Bt + (size_t)(n0 + lr) * K + k0 + lk);
        As[lk+0][lr] = a4.x; As[lk+1][lr] = a4.y; As[lk+2][lr] = a4.z; As[lk+3][lr] = a4.w;
        Bs[lk+0][lr] = b4.x; Bs[lk+1][lr] = b4.y; Bs[lk+2][lr] = b4.z; Bs[lk+3][lr] = b4.w;
        __syncthreads();
        #pragma unroll
        for (int kk = 0; kk < 16; kk++) {
            float4 av = *(const float4*)&As[kk][ty * 4];
            float4 bv = *(const float4*)&Bs[kk][tx * 4];
            float a[4] = {av.x, av.y, av.z, av.w};
            float b[4] = {bv.x, bv.y, bv.z, bv.w};
            #pragma unroll
            for (int i = 0; i < 4; i++)
                #pragma unroll
                for (int j = 0; j < 4; j++) acc[i][j] += a[i] * b[j];
        }
        __syncthreads();
    }
    int c0 = n0 + tx * 4;
    float4 bsv = *(const float4*)(bias + c0);
    #pragma unroll
    for (int i = 0; i < 4; i++) {
        int r = m0 + ty * 4 + i;
        float4 o;
        o.x = acc[i][0] + bsv.x; o.y = acc[i][1] + bsv.y;
        o.z = acc[i][2] + bsv.z; o.w = acc[i][3] + bsv.w;
        *(float4*)(C + (size_t)r * N + c0) = o;
    }
}

// ---------------- MoE GEMM: per-expert C = A @ B + bias, dynamic M = g_cnt[e] ----------------
// A stride per expert CAP*K, B stride K*N, C stride CAP*N. grid (N/64, CAP/64, E).
__global__ __launch_bounds__(256) void gemm_moe(
    const float* __restrict__ Aall, const float* __restrict__ Ball,
    const float* __restrict__ biasall, float* __restrict__ Call,
    int K, int N, int relu)
{
    int e = blockIdx.z;
    int m_e = g_cnt[e];
    int m0 = blockIdx.y * 64;
    if (m0 >= m_e) return;
    const float* A    = Aall    + (size_t)e * CAPN * K;
    const float* Bm   = Ball    + (size_t)e * K * N;
    const float* bias = biasall + (size_t)e * N;
    float*       C    = Call    + (size_t)e * CAPN * N;

    __shared__ float As[16][68];
    __shared__ float Bs[16][68];
    int tid = threadIdx.x;
    int tx = tid & 15, ty = tid >> 4;
    int n0 = blockIdx.x * 64;
    int lr = tid >> 2, lk = (tid & 3) * 4;     // A loader
    int bk = tid >> 4, bn = (tid & 15) * 4;    // B loader
    float acc[4][4];
    #pragma unroll
    for (int i = 0; i < 4; i++)
        #pragma unroll
        for (int j = 0; j < 4; j++) acc[i][j] = 0.f;

    for (int k0 = 0; k0 < K; k0 += 16) {
        float4 a4 = *(const float4*)(A + (size_t)(m0 + lr) * K + k0 + lk);
        As[lk+0][lr] = a4.x; As[lk+1][lr] = a4.y; As[lk+2][lr] = a4.z; As[lk+3][lr] = a4.w;
        float4 b4 = *(const float4*)(Bm + (size_t)(k0 + bk) * N + n0 + bn);
        *(float4*)&Bs[bk][bn] = b4;
        __syncthreads();
        #pragma unroll
        for (int kk = 0; kk < 16; kk++) {
            float4 av = *(const float4*)&As[kk][ty * 4];
            float4 bv = *(const float4*)&Bs[kk][tx * 4];
            float a[4] = {av.x, av.y, av.z, av.w};
            float b[4] = {bv.x, bv.y, bv.z, bv.w};
            #pragma unroll
            for (int i = 0; i < 4; i++)
                #pragma unroll
                for (int j = 0; j < 4; j++) acc[i][j] += a[i] * b[j];
        }
        __syncthreads();
    }
    int c0 = n0 + tx * 4;
    float4 bsv = *(const float4*)(bias + c0);
    #pragma unroll
    for (int i = 0; i < 4; i++) {
        int r = m0 + ty * 4 + i;
        if (r < m_e) {
            float4 o;
            o.x = acc[i][0] + bsv.x; o.y = acc[i][1] + bsv.y;
            o.z = acc[i][2] + bsv.z; o.w = acc[i][3] + bsv.w;
            if (relu) {
                o.x = fmaxf(o.x, 0.f); o.y = fmaxf(o.y, 0.f);
                o.z = fmaxf(o.z, 0.f); o.w = fmaxf(o.w, 0.f);
            }
            *(float4*)(C + (size_t)r * N + c0) = o;
        }
    }
}

// ---------------- attention: flash-style, 1 thread = 1 query ----------------
// grid (S/64, B*H), block 64.
__global__ __launch_bounds__(64) void attn_kernel(
    const float* __restrict__ qkv, float* __restrict__ ctx)
{
    __shared__ float Ks[64][64];
    __shared__ float Vs[64][64];
    int bh = blockIdx.y;
    int b = bh / HH, h = bh % HH;
    int tid = threadIdx.x;
    int s = blockIdx.x * 64 + tid;

    const float* qrow = qkv + ((size_t)s * BB + b) * (3 * DD) + h * DHH;
    float q[64];
    #pragma unroll
    for (int i = 0; i < 16; i++) {
        float4 t4 = *(const float4*)(qrow + i * 4);
        q[i*4+0] = t4.x; q[i*4+1] = t4.y; q[i*4+2] = t4.z; q[i*4+3] = t4.w;
    }
    float mrun = -1e30f, l = 0.f;
    float acc[64];
    #pragma unroll
    for (int i = 0; i < 64; i++) acc[i] = 0.f;

    for (int kt = 0; kt < SS; kt += 64) {
        int t = kt + tid;
        const float* krow = qkv + ((size_t)t * BB + b) * (3 * DD) + DD + h * DHH;
        const float* vrow = krow + DD;
        // XOR swizzle at float4 granularity: conflict-free STS.128, broadcast LDS
        #pragma unroll
        for (int i = 0; i < 16; i++) {
            int sw = i ^ (tid & 15);
            *(float4*)&Ks[tid][sw * 4] = *(const float4*)(krow + i * 4);
            *(float4*)&Vs[tid][sw * 4] = *(const float4*)(vrow + i * 4);
        }
        __syncthreads();
        #pragma unroll 4
        for (int j = 0; j < 64; j++) {
            float sc = 0.f;
            #pragma unroll
            for (int i = 0; i < 16; i++) {
                float4 k4 = *(const float4*)&Ks[j][(i ^ (j & 15)) * 4];
                sc += q[i*4+0]*k4.x + q[i*4+1]*k4.y + q[i*4+2]*k4.z + q[i*4+3]*k4.w;
            }
            sc *= 0.125f;   // 1/sqrt(64)
            if (sc > mrun) {
                float scale = __expf(mrun - sc);
                l *= scale;
                #pragma unroll
                for (int i = 0; i < 64; i++) acc[i] *= scale;
                mrun = sc;
            }
            float p = __expf(sc - mrun);
            l += p;
            #pragma unroll
            for (int i = 0; i < 16; i++) {
                float4 v4 = *(const float4*)&Vs[j][(i ^ (j & 15)) * 4];
                acc[i*4+0] += p * v4.x; acc[i*4+1] += p * v4.y;
                acc[i*4+2] += p * v4.z; acc[i*4+3] += p * v4.w;
            }
        }
        __syncthreads();
    }
    float inv = 1.f / l;
    float* crow = ctx + ((size_t)s * BB + b) * DD + h * DHH;
    #pragma unroll
    for (int i = 0; i < 16; i++) {
        float4 o;
        o.x = acc[i*4+0]*inv; o.y = acc[i*4+1]*inv;
        o.z = acc[i*4+2]*inv; o.w = acc[i*4+3]*inv;
        *(float4*)(crow + i * 4) = o;
    }
}

// ---------------- out = LayerNorm(a + b) ----------------
__global__ __launch_bounds__(256) void add_ln_kernel(
    const float* __restrict__ a, const float* __restrict__ bvec,
    const float* __restrict__ g, const float* __restrict__ beta,
    float* __restrict__ out)
{
    int t = blockIdx.x;
    __shared__ float row[DD];
    __shared__ float red[256];
    int tid = threadIdx.x;
    float s = 0.f;
    for (int d = tid; d < DD; d += 256) {
        float v = a[(size_t)t * DD + d] + bvec[(size_t)t * DD + d];
        row[d] = v; s += v;
    }
    red[tid] = s; __syncthreads();
    for (int o = 128; o > 0; o >>= 1) { if (tid < o) red[tid] += red[tid + o]; __syncthreads(); }
    float mean = red[0] * (1.f / DD);
    __syncthreads();
    float vs = 0.f;
    for (int d = tid; d < DD; d += 256) { float dv = row[d] - mean; vs += dv * dv; }
    red[tid] = vs; __syncthreads();
    for (int o = 128; o > 0; o >>= 1) { if (tid < o) red[tid] += red[tid + o]; __syncthreads(); }
    float rstd = rsqrtf(red[0] * (1.f / DD) + 1e-5f);
    for (int d = tid; d < DD; d += 256)
        out[(size_t)t * DD + d] = (row[d] - mean) * rstd * g[d] + beta[d];
}

// ---------------- router: warp per token ----------------
__global__ __launch_bounds__(256) void router_kernel(
    const float* __restrict__ x, const float* __restrict__ rw,
    const float* __restrict__ rb)
{
    int warp = threadIdx.x >> 5, lane = threadIdx.x & 31;
    int t = blockIdx.x * 8 + warp;
    __shared__ float sprob[EE];
    if (threadIdx.x < EE) sprob[threadIdx.x] = 0.f;
    __syncthreads();

    float pe[EE];
    #pragma unroll
    for (int e = 0; e < EE; e++) pe[e] = 0.f;
    const float* xr = x + (size_t)t * DD;
    for (int d = lane; d < DD; d += 32) {
        float xv = xr[d];
        #pragma unroll
        for (int e = 0; e < EE; e++) pe[e] += xv * rw[e * DD + d];
    }
    #pragma unroll
    for (int e = 0; e < EE; e++)
        #pragma unroll
        for (int o = 16; o > 0; o >>= 1) pe[e] += __shfl_xor_sync(0xffffffffu, pe[e], o);

    if (lane == 0) {
        float mx = -1e30f;
        #pragma unroll
        for (int e = 0; e < EE; e++) { pe[e] += rb[e]; mx = fmaxf(mx, pe[e]); }
        float p[EE]; float sum = 0.f;
        #pragma unroll
        for (int e = 0; e < EE; e++) { p[e] = __expf(pe[e] - mx); sum += p[e]; }
        float inv = 1.f / sum;
        int best = 0; float bp = -1.f;
        #pragma unroll
        for (int e = 0; e < EE; e++) { p[e] *= inv; }
        #pragma unroll
        for (int e = 0; e < EE; e++) { if (p[e] > bp) { bp = p[e]; best = e; } }
        g_eidx[t] = best; g_gate[t] = bp;
        #pragma unroll
        for (int e = 0; e < EE; e++) atomicAdd(&sprob[e], p[e]);
    }
    __syncthreads();
    if (threadIdx.x < EE) atomicAdd(&g_probsum[threadIdx.x], sprob[threadIdx.x]);
}

// ---------------- per-expert queue positions (warp ballot scan) ----------------
__global__ void pos_kernel() {
    int warp = threadIdx.x >> 5, lane = threadIdx.x & 31;
    if (warp >= EE) return;
    int base = 0;
    for (int t0 = 0; t0 < TT; t0 += 32) {
        int t = t0 + lane;
        bool m = (g_eidx[t] == warp);
        unsigned msk = __ballot_sync(0xffffffffu, m);
        if (m) g_pos[t] = base + __popc(msk & ((1u << lane) - 1u));
        base += __popc(msk);
    }
    if (lane == 0) {
        g_cntfull[warp] = base;
        g_cnt[warp] = base < CAPN ? base : CAPN;
    }
}

// ---------------- gather tokens into expert buffers ----------------
__global__ __launch_bounds__(192) void gather_kernel(const float* __restrict__ x) {
    int t = blockIdx.x;
    int p = g_pos[t];
    if (p >= CAPN) return;
    int e = g_eidx[t];
    float4* dst = (float4*)(g_buf + ((size_t)e * CAPN + p) * DD);
    const float4* src = (const float4*)(x + (size_t)t * DD);
    dst[threadIdx.x] = src[threadIdx.x];
}

// ---------------- final: out = LN(x + gate * y[eidx,pos]) ----------------
__global__ __launch_bounds__(256) void final_kernel(
    const float* __restrict__ x, const float* __restrict__ g,
    const float* __restrict__ beta, float* __restrict__ out)
{
    int t = blockIdx.x;
    __shared__ float row[DD];
    __shared__ float red[256];
    int tid = threadIdx.x;
    int p = g_pos[t], e = g_eidx[t];
    float ga = g_gate[t];
    bool keep = (p < CAPN);
    const float* yrow = g_y + ((size_t)e * CAPN + (keep ? p : 0)) * DD;

    float s = 0.f;
    for (int d = tid; d < DD; d += 256) {
        float v = x[(size_t)t * DD + d] + (keep ? ga * yrow[d] : 0.f);
        row[d] = v; s += v;
    }
    red[tid] = s; __syncthreads();
    for (int o = 128; o > 0; o >>= 1) { if (tid < o) red[tid] += red[tid + o]; __syncthreads(); }
    float mean = red[0] * (1.f / DD);
    __syncthreads();
    float vs = 0.f;
    for (int d = tid; d < DD; d += 256) { float dv = row[d] - mean; vs += dv * dv; }
    red[tid] = vs; __syncthreads();
    for (int o = 128; o > 0; o >>= 1) { if (tid < o) red[tid] += red[tid + o]; __syncthreads(); }
    float rstd = rsqrtf(red[0] * (1.f / DD) + 1e-5f);
    for (int d = tid; d < DD; d += 256)
        out[(size_t)t * DD + d] = (row[d] - mean) * rstd * g[d] + beta[d];
}

// ---------------- lb loss ----------------
__global__ void loss_kernel(float* __restrict__ out) {
    float acc = 0.f;
    for (int e = 0; e < EE; e++)
        acc += ((float)g_cntfull[e] / (float)TT) * (g_probsum[e] / (float)TT);
    out[(size_t)TT * DD] = (float)EE * acc;
}

// ---------------- launch ----------------
extern "C" void kernel_launch(void* const* d_in, const int* in_sizes, int n_in,
                              void* d_out, int out_size)
{
    const float* src   = (const float*)d_in[0];
    const float* inw   = (const float*)d_in[1];
    const float* inb   = (const float*)d_in[2];
    const float* outw  = (const float*)d_in[3];
    const float* outb  = (const float*)d_in[4];
    const float* n1g   = (const float*)d_in[5];
    const float* n1b   = (const float*)d_in[6];
    const float* rw    = (const float*)d_in[7];
    const float* rb    = (const float*)d_in[8];
    const float* w1    = (const float*)d_in[9];
    const float* b1    = (const float*)d_in[10];
    const float* w2    = (const float*)d_in[11];
    const float* b2    = (const float*)d_in[12];
    const float* n2g   = (const float*)d_in[13];
    const float* n2b   = (const float*)d_in[14];
    float* out = (float*)d_out;

    float *p_qkv, *p_ctx, *p_attn, *p_x, *p_buf, *p_h, *p_y;
    cudaGetSymbolAddress((void**)&p_qkv,  g_qkv);
    cudaGetSymbolAddress((void**)&p_ctx,  g_ctx);
    cudaGetSymbolAddress((void**)&p_attn, g_attn);
    cudaGetSymbolAddress((void**)&p_x,    g_x);
    cudaGetSymbolAddress((void**)&p_buf,  g_buf);
    cudaGetSymbolAddress((void**)&p_h,    g_h);
    cudaGetSymbolAddress((void**)&p_y,    g_y);

    zero_kernel<<<1, 32>>>();

    // QKV = src @ in_proj_w^T + b   [4096, 2304]
    gemm_abt<<<dim3((3 * DD) / 64, TT / 64), 256>>>(src, inw, inb, p_qkv, 3 * DD, DD);

    // attention -> ctx [T, D]
    attn_kernel<<<dim3(SS / 64, BB * HH), 64>>>(p_qkv, p_ctx);

    // attn_out = ctx @ out_proj_w^T + b
    gemm_abt<<<dim3(DD / 64, TT / 64), 256>>>(p_ctx, outw, outb, p_attn, DD, DD);

    // x = LN(src + attn_out)
    add_ln_kernel<<<TT, 256>>>(src, p_attn, n1g, n1b, p_x);

    // routing
    router_kernel<<<TT / 8, 256>>>(p_x, rw, rb);
    pos_kernel<<<1, 256>>>();
    gather_kernel<<<TT, 192>>>(p_x);

    // expert FFN
    gemm_moe<<<dim3(FF / 64, CAPN / 64, EE), 256>>>(p_buf, w1, b1, p_h, DD, FF, 1);
    gemm_moe<<<dim3(DD / 64, CAPN / 64, EE), 256>>>(p_h, w2, b2, p_y, FF, DD, 0);

    // out = LN(x + gate*moe)
    final_kernel<<<TT, 256>>>(p_x, n2g, n2b, out);
    loss_kernel<<<1, 1>>>(out);
}

// round 4
// speedup vs baseline: 1.3944x; 1.3944x over previous
#include <cuda_runtime.h>
#include <math.h>
#include <stdint.h>

// ---------------- problem constants ----------------
#define SS   2048
#define BB   2
#define DD   768
#define HH   12
#define DHH  64
#define FF   3072
#define EE   8
#define TT   4096            // S*B
#define CAPN 1024            // capacity

// ---------------- device scratch (allowed: __device__ globals) ----------------
__device__ float g_qkv [(size_t)TT * 3 * DD];     // [T, 2304]
__device__ float g_ctx [(size_t)TT * DD];         // attention context [T, D]
__device__ float g_attn[(size_t)TT * DD];         // attn out-proj     [T, D]
__device__ float g_x   [(size_t)TT * DD];         // post-LN1          [T, D]
__device__ float g_buf [(size_t)EE * CAPN * DD];  // expert input buffers
__device__ float g_h   [(size_t)EE * CAPN * FF];  // expert hidden
__device__ float g_y   [(size_t)EE * CAPN * DD];  // expert output
__device__ int   g_eidx[TT];
__device__ int   g_pos [TT];
__device__ float g_gate[TT];
__device__ int   g_cnt    [EE];                   // min(count, CAP)
__device__ int   g_cntfull[EE];                   // full count (for lb loss)
__device__ float g_probsum[EE];

// ---------------- helpers ----------------
__device__ __forceinline__ float to_tf32(float x) {
    uint32_t u;
    asm("cvt.rna.tf32.f32 %0, %1;" : "=r"(u) : "f"(x));
    return __uint_as_float(u);
}

__device__ __forceinline__ void mma_tf32(
    float& c0, float& c1, float& c2, float& c3,
    uint32_t a0, uint32_t a1, uint32_t a2, uint32_t a3,
    uint32_t b0, uint32_t b1)
{
    asm volatile(
        "mma.sync.aligned.m16n8k8.row.col.f32.tf32.tf32.f32 "
        "{%0,%1,%2,%3}, {%4,%5,%6,%7}, {%8,%9}, {%0,%1,%2,%3};"
        : "+f"(c0), "+f"(c1), "+f"(c2), "+f"(c3)
        : "r"(a0), "r"(a1), "r"(a2), "r"(a3), "r"(b0), "r"(b1));
}

// ---------------- zero accumulators ----------------
__global__ void zero_kernel() {
    if (threadIdx.x < EE) g_probsum[threadIdx.x] = 0.f;
}

// ======================================================================
// TF32 tensor-core GEMM.
//   BLAYOUT=1: B given as Bt[N][K] (computes A @ Bt^T)
//   BLAYOUT=0: B given as B[K][N]  (computes A @ B)
//   MOE=true : per-expert via blockIdx.z, dynamic M = g_cnt[e]
// Block tile 128x128, K-tile 32, 256 threads = 8 warps (2x4), warp 64x32.
// ======================================================================
template<int BLAYOUT, bool MOE>
__global__ __launch_bounds__(256) void gemm_tf32(
    const float* __restrict__ Aall, const float* __restrict__ Ball,
    const float* __restrict__ biasall, float* __restrict__ Call,
    int K, int N, int relu)
{
    __shared__ float As[128][36];    // stride 36 == 4 (mod 32): conflict-free a-frags
    __shared__ float Bs[32][136];    // stride 136 == 8 (mod 32): conflict-free b-frags

    const int tid  = threadIdx.x;
    const int lane = tid & 31;
    const int warp = tid >> 5;
    const int wm = (warp & 1) * 64;
    const int wn = (warp >> 1) * 32;

    const int n0 = blockIdx.x * 128;
    const int m0 = blockIdx.y * 128;

    const float* A; const float* B; const float* bias; float* C;
    int mlim;
    if (MOE) {
        int e = blockIdx.z;
        int m_e = g_cnt[e];
        if (m0 >= m_e) return;
        mlim = m_e;
        A    = Aall    + (size_t)e * CAPN * K;
        B    = Ball    + (size_t)e * K * N;
        bias = biasall + (size_t)e * N;
        C    = Call    + (size_t)e * CAPN * N;
    } else {
        mlim = 1 << 30;
        A = Aall; B = Ball; bias = biasall; C = Call;
    }

    // ---- staging thread mapping ----
    const int ar = tid >> 1;              // A: row 0..127
    const int ak = (tid & 1) * 16;        // A: k half
    // BLAYOUT==1 : bn_t = tid>>1 (n), bk_t = (tid&1)*16
    // BLAYOUT==0 : bk_r = tid>>3 (k), bn_r = (tid&7)*16
    const int bn_t = tid >> 1;
    const int bk_t = (tid & 1) * 16;
    const int bk_r = tid >> 3;
    const int bn_r = (tid & 7) * 16;

    float4 areg[4], breg[4];

    auto ldg_tile = [&](int k0) {
        const float* ap = A + (size_t)(m0 + ar) * K + k0 + ak;
        #pragma unroll
        for (int i = 0; i < 4; i++) areg[i] = *(const float4*)(ap + 4 * i);
        if (BLAYOUT == 1) {
            const float* bp = B + (size_t)(n0 + bn_t) * K + k0 + bk_t;
            #pragma unroll
            for (int i = 0; i < 4; i++) breg[i] = *(const float4*)(bp + 4 * i);
        } else {
            const float* bp = B + (size_t)(k0 + bk_r) * N + n0 + bn_r;
            #pragma unroll
            for (int i = 0; i < 4; i++) breg[i] = *(const float4*)(bp + 4 * i);
        }
    };

    auto sts_tile = [&]() {
        #pragma unroll
        for (int i = 0; i < 4; i++) {
            float* dst = &As[ar][ak + 4 * i];
            dst[0] = to_tf32(areg[i].x); dst[1] = to_tf32(areg[i].y);
            dst[2] = to_tf32(areg[i].z); dst[3] = to_tf32(areg[i].w);
        }
        if (BLAYOUT == 1) {
            #pragma unroll
            for (int i = 0; i < 4; i++) {
                Bs[bk_t + 4*i + 0][bn_t] = to_tf32(breg[i].x);
                Bs[bk_t + 4*i + 1][bn_t] = to_tf32(breg[i].y);
                Bs[bk_t + 4*i + 2][bn_t] = to_tf32(breg[i].z);
                Bs[bk_t + 4*i + 3][bn_t] = to_tf32(breg[i].w);
            }
        } else {
            #pragma unroll
            for (int i = 0; i < 4; i++) {
                float* dst = &Bs[bk_r][bn_r + 4 * i];
                dst[0] = to_tf32(breg[i].x); dst[1] = to_tf32(breg[i].y);
                dst[2] = to_tf32(breg[i].z); dst[3] = to_tf32(breg[i].w);
            }
        }
    };

    float acc[4][4][4];
    #pragma unroll
    for (int mi = 0; mi < 4; mi++)
        #pragma unroll
        for (int ni = 0; ni < 4; ni++)
            #pragma unroll
            for (int r = 0; r < 4; r++) acc[mi][ni][r] = 0.f;

    ldg_tile(0);
    sts_tile();
    __syncthreads();

    const int ntiles = K >> 5;
    for (int t = 0; t < ntiles; t++) {
        bool more = (t + 1 < ntiles);
        if (more) ldg_tile((t + 1) << 5);   // overlap global latency with compute

        #pragma unroll
        for (int ks = 0; ks < 4; ks++) {
            uint32_t a[4][4], b[4][2];
            #pragma unroll
            for (int mi = 0; mi < 4; mi++) {
                int r = wm + mi * 16 + (lane >> 2);
                int c = ks * 8 + (lane & 3);
                a[mi][0] = __float_as_uint(As[r    ][c    ]);
                a[mi][1] = __float_as_uint(As[r + 8][c    ]);
                a[mi][2] = __float_as_uint(As[r    ][c + 4]);
                a[mi][3] = __float_as_uint(As[r + 8][c + 4]);
            }
            #pragma unroll
            for (int ni = 0; ni < 4; ni++) {
                int br = ks * 8 + (lane & 3);
                int bc = wn + ni * 8 + (lane >> 2);
                b[ni][0] = __float_as_uint(Bs[br    ][bc]);
                b[ni][1] = __float_as_uint(Bs[br + 4][bc]);
            }
            #pragma unroll
            for (int mi = 0; mi < 4; mi++)
                #pragma unroll
                for (int ni = 0; ni < 4; ni++)
                    mma_tf32(acc[mi][ni][0], acc[mi][ni][1],
                             acc[mi][ni][2], acc[mi][ni][3],
                             a[mi][0], a[mi][1], a[mi][2], a[mi][3],
                             b[ni][0], b[ni][1]);
        }
        __syncthreads();
        if (more) {
            sts_tile();
            __syncthreads();
        }
    }

    // ---- epilogue: bias (+relu), guarded stores ----
    #pragma unroll
    for (int mi = 0; mi < 4; mi++) {
        int r0 = m0 + wm + mi * 16 + (lane >> 2);
        #pragma unroll
        for (int ni = 0; ni < 4; ni++) {
            int c = n0 + wn + ni * 8 + 2 * (lane & 3);
            float bx = bias[c], by = bias[c + 1];
            float v0 = acc[mi][ni][0] + bx, v1 = acc[mi][ni][1] + by;
            float v2 = acc[mi][ni][2] + bx, v3 = acc[mi][ni][3] + by;
            if (relu) {
                v0 = fmaxf(v0, 0.f); v1 = fmaxf(v1, 0.f);
                v2 = fmaxf(v2, 0.f); v3 = fmaxf(v3, 0.f);
            }
            if (r0 < mlim)     *(float2*)(C + (size_t)r0 * N + c)       = make_float2(v0, v1);
            if (r0 + 8 < mlim) *(float2*)(C + (size_t)(r0 + 8) * N + c) = make_float2(v2, v3);
        }
    }
}

// ---------------- attention: flash-style, 1 thread = 1 query ----------------
__global__ __launch_bounds__(64) void attn_kernel(
    const float* __restrict__ qkv, float* __restrict__ ctx)
{
    __shared__ float Ks[64][64];
    __shared__ float Vs[64][64];
    int bh = blockIdx.y;
    int b = bh / HH, h = bh % HH;
    int tid = threadIdx.x;
    int s = blockIdx.x * 64 + tid;

    const float* qrow = qkv + ((size_t)s * BB + b) * (3 * DD) + h * DHH;
    float q[64];
    #pragma unroll
    for (int i = 0; i < 16; i++) {
        float4 t4 = *(const float4*)(qrow + i * 4);
        q[i*4+0] = t4.x; q[i*4+1] = t4.y; q[i*4+2] = t4.z; q[i*4+3] = t4.w;
    }
    float mrun = -1e30f, l = 0.f;
    float acc[64];
    #pragma unroll
    for (int i = 0; i < 64; i++) acc[i] = 0.f;

    for (int kt = 0; kt < SS; kt += 64) {
        int t = kt + tid;
        const float* krow = qkv + ((size_t)t * BB + b) * (3 * DD) + DD + h * DHH;
        const float* vrow = krow + DD;
        #pragma unroll
        for (int i = 0; i < 16; i++) {
            int sw = i ^ (tid & 15);
            *(float4*)&Ks[tid][sw * 4] = *(const float4*)(krow + i * 4);
            *(float4*)&Vs[tid][sw * 4] = *(const float4*)(vrow + i * 4);
        }
        __syncthreads();
        #pragma unroll 4
        for (int j = 0; j < 64; j++) {
            float sc = 0.f;
            #pragma unroll
            for (int i = 0; i < 16; i++) {
                float4 k4 = *(const float4*)&Ks[j][(i ^ (j & 15)) * 4];
                sc += q[i*4+0]*k4.x + q[i*4+1]*k4.y + q[i*4+2]*k4.z + q[i*4+3]*k4.w;
            }
            sc *= 0.125f;
            if (sc > mrun) {
                float scale = __expf(mrun - sc);
                l *= scale;
                #pragma unroll
                for (int i = 0; i < 64; i++) acc[i] *= scale;
                mrun = sc;
            }
            float p = __expf(sc - mrun);
            l += p;
            #pragma unroll
            for (int i = 0; i < 16; i++) {
                float4 v4 = *(const float4*)&Vs[j][(i ^ (j & 15)) * 4];
                acc[i*4+0] += p * v4.x; acc[i*4+1] += p * v4.y;
                acc[i*4+2] += p * v4.z; acc[i*4+3] += p * v4.w;
            }
        }
        __syncthreads();
    }
    float inv = 1.f / l;
    float* crow = ctx + ((size_t)s * BB + b) * DD + h * DHH;
    #pragma unroll
    for (int i = 0; i < 16; i++) {
        float4 o;
        o.x = acc[i*4+0]*inv; o.y = acc[i*4+1]*inv;
        o.z = acc[i*4+2]*inv; o.w = acc[i*4+3]*inv;
        *(float4*)(crow + i * 4) = o;
    }
}

// ---------------- out = LayerNorm(a + b) ----------------
__global__ __launch_bounds__(256) void add_ln_kernel(
    const float* __restrict__ a, const float* __restrict__ bvec,
    const float* __restrict__ g, const float* __restrict__ beta,
    float* __restrict__ out)
{
    int t = blockIdx.x;
    __shared__ float row[DD];
    __shared__ float red[256];
    int tid = threadIdx.x;
    float s = 0.f;
    for (int d = tid; d < DD; d += 256) {
        float v = a[(size_t)t * DD + d] + bvec[(size_t)t * DD + d];
        row[d] = v; s += v;
    }
    red[tid] = s; __syncthreads();
    for (int o = 128; o > 0; o >>= 1) { if (tid < o) red[tid] += red[tid + o]; __syncthreads(); }
    float mean = red[0] * (1.f / DD);
    __syncthreads();
    float vs = 0.f;
    for (int d = tid; d < DD; d += 256) { float dv = row[d] - mean; vs += dv * dv; }
    red[tid] = vs; __syncthreads();
    for (int o = 128; o > 0; o >>= 1) { if (tid < o) red[tid] += red[tid + o]; __syncthreads(); }
    float rstd = rsqrtf(red[0] * (1.f / DD) + 1e-5f);
    for (int d = tid; d < DD; d += 256)
        out[(size_t)t * DD + d] = (row[d] - mean) * rstd * g[d] + beta[d];
}

// ---------------- router: warp per token ----------------
__global__ __launch_bounds__(256) void router_kernel(
    const float* __restrict__ x, const float* __restrict__ rw,
    const float* __restrict__ rb)
{
    int warp = threadIdx.x >> 5, lane = threadIdx.x & 31;
    int t = blockIdx.x * 8 + warp;
    __shared__ float sprob[EE];
    if (threadIdx.x < EE) sprob[threadIdx.x] = 0.f;
    __syncthreads();

    float pe[EE];
    #pragma unroll
    for (int e = 0; e < EE; e++) pe[e] = 0.f;
    const float* xr = x + (size_t)t * DD;
    for (int d = lane; d < DD; d += 32) {
        float xv = xr[d];
        #pragma unroll
        for (int e = 0; e < EE; e++) pe[e] += xv * rw[e * DD + d];
    }
    #pragma unroll
    for (int e = 0; e < EE; e++)
        #pragma unroll
        for (int o = 16; o > 0; o >>= 1) pe[e] += __shfl_xor_sync(0xffffffffu, pe[e], o);

    if (lane == 0) {
        float mx = -1e30f;
        #pragma unroll
        for (int e = 0; e < EE; e++) { pe[e] += rb[e]; mx = fmaxf(mx, pe[e]); }
        float p[EE]; float sum = 0.f;
        #pragma unroll
        for (int e = 0; e < EE; e++) { p[e] = __expf(pe[e] - mx); sum += p[e]; }
        float inv = 1.f / sum;
        int best = 0; float bp = -1.f;
        #pragma unroll
        for (int e = 0; e < EE; e++) { p[e] *= inv; }
        #pragma unroll
        for (int e = 0; e < EE; e++) { if (p[e] > bp) { bp = p[e]; best = e; } }
        g_eidx[t] = best; g_gate[t] = bp;
        #pragma unroll
        for (int e = 0; e < EE; e++) atomicAdd(&sprob[e], p[e]);
    }
    __syncthreads();
    if (threadIdx.x < EE) atomicAdd(&g_probsum[threadIdx.x], sprob[threadIdx.x]);
}

// ---------------- per-expert queue positions (warp ballot scan) ----------------
__global__ void pos_kernel() {
    int warp = threadIdx.x >> 5, lane = threadIdx.x & 31;
    if (warp >= EE) return;
    int base = 0;
    for (int t0 = 0; t0 < TT; t0 += 32) {
        int t = t0 + lane;
        bool m = (g_eidx[t] == warp);
        unsigned msk = __ballot_sync(0xffffffffu, m);
        if (m) g_pos[t] = base + __popc(msk & ((1u << lane) - 1u));
        base += __popc(msk);
    }
    if (lane == 0) {
        g_cntfull[warp] = base;
        g_cnt[warp] = base < CAPN ? base : CAPN;
    }
}

// ---------------- gather tokens into expert buffers ----------------
__global__ __launch_bounds__(192) void gather_kernel(const float* __restrict__ x) {
    int t = blockIdx.x;
    int p = g_pos[t];
    if (p >= CAPN) return;
    int e = g_eidx[t];
    float4* dst = (float4*)(g_buf + ((size_t)e * CAPN + p) * DD);
    const float4* src = (const float4*)(x + (size_t)t * DD);
    dst[threadIdx.x] = src[threadIdx.x];
}

// ---------------- final: out = LN(x + gate * y[eidx,pos]) ----------------
__global__ __launch_bounds__(256) void final_kernel(
    const float* __restrict__ x, const float* __restrict__ g,
    const float* __restrict__ beta, float* __restrict__ out)
{
    int t = blockIdx.x;
    __shared__ float row[DD];
    __shared__ float red[256];
    int tid = threadIdx.x;
    int p = g_pos[t], e = g_eidx[t];
    float ga = g_gate[t];
    bool keep = (p < CAPN);
    const float* yrow = g_y + ((size_t)e * CAPN + (keep ? p : 0)) * DD;

    float s = 0.f;
    for (int d = tid; d < DD; d += 256) {
        float v = x[(size_t)t * DD + d] + (keep ? ga * yrow[d] : 0.f);
        row[d] = v; s += v;
    }
    red[tid] = s; __syncthreads();
    for (int o = 128; o > 0; o >>= 1) { if (tid < o) red[tid] += red[tid + o]; __syncthreads(); }
    float mean = red[0] * (1.f / DD);
    __syncthreads();
    float vs = 0.f;
    for (int d = tid; d < DD; d += 256) { float dv = row[d] - mean; vs += dv * dv; }
    red[tid] = vs; __syncthreads();
    for (int o = 128; o > 0; o >>= 1) { if (tid < o) red[tid] += red[tid + o]; __syncthreads(); }
    float rstd = rsqrtf(red[0] * (1.f / DD) + 1e-5f);
    for (int d = tid; d < DD; d += 256)
        out[(size_t)t * DD + d] = (row[d] - mean) * rstd * g[d] + beta[d];
}

// ---------------- lb loss ----------------
__global__ void loss_kernel(float* __restrict__ out) {
    float acc = 0.f;
    for (int e = 0; e < EE; e++)
        acc += ((float)g_cntfull[e] / (float)TT) * (g_probsum[e] / (float)TT);
    out[(size_t)TT * DD] = (float)EE * acc;
}

// ---------------- launch ----------------
extern "C" void kernel_launch(void* const* d_in, const int* in_sizes, int n_in,
                              void* d_out, int out_size)
{
    const float* src   = (const float*)d_in[0];
    const float* inw   = (const float*)d_in[1];
    const float* inb   = (const float*)d_in[2];
    const float* outw  = (const float*)d_in[3];
    const float* outb  = (const float*)d_in[4];
    const float* n1g   = (const float*)d_in[5];
    const float* n1b   = (const float*)d_in[6];
    const float* rw    = (const float*)d_in[7];
    const float* rb    = (const float*)d_in[8];
    const float* w1    = (const float*)d_in[9];
    const float* b1    = (const float*)d_in[10];
    const float* w2    = (const float*)d_in[11];
    const float* b2    = (const float*)d_in[12];
    const float* n2g   = (const float*)d_in[13];
    const float* n2b   = (const float*)d_in[14];
    float* out = (float*)d_out;

    float *p_qkv, *p_ctx, *p_attn, *p_x, *p_buf, *p_h, *p_y;
    cudaGetSymbolAddress((void**)&p_qkv,  g_qkv);
    cudaGetSymbolAddress((void**)&p_ctx,  g_ctx);
    cudaGetSymbolAddress((void**)&p_attn, g_attn);
    cudaGetSymbolAddress((void**)&p_x,    g_x);
    cudaGetSymbolAddress((void**)&p_buf,  g_buf);
    cudaGetSymbolAddress((void**)&p_h,    g_h);
    cudaGetSymbolAddress((void**)&p_y,    g_y);

    zero_kernel<<<1, 32>>>();

    // QKV = src @ in_proj_w^T + b   [4096, 2304]  (tf32 tensor cores)
    gemm_tf32<1, false><<<dim3((3 * DD) / 128, TT / 128), 256>>>(
        src, inw, inb, p_qkv, DD, 3 * DD, 0);

    // attention -> ctx [T, D]
    attn_kernel<<<dim3(SS / 64, BB * HH), 64>>>(p_qkv, p_ctx);

    // attn_out = ctx @ out_proj_w^T + b
    gemm_tf32<1, false><<<dim3(DD / 128, TT / 128), 256>>>(
        p_ctx, outw, outb, p_attn, DD, DD, 0);

    // x = LN(src + attn_out)
    add_ln_kernel<<<TT, 256>>>(src, p_attn, n1g, n1b, p_x);

    // routing
    router_kernel<<<TT / 8, 256>>>(p_x, rw, rb);
    pos_kernel<<<1, 256>>>();
    gather_kernel<<<TT, 192>>>(p_x);

    // expert FFN (tf32 tensor cores, dynamic per-expert M)
    gemm_tf32<0, true><<<dim3(FF / 128, CAPN / 128, EE), 256>>>(
        p_buf, w1, b1, p_h, DD, FF, 1);
    gemm_tf32<0, true><<<dim3(DD / 128, CAPN / 128, EE), 256>>>(
        p_h, w2, b2, p_y, FF, DD, 0);

    // out = LN(x + gate*moe)
    final_kernel<<<TT, 256>>>(p_x, n2g, n2b, out);
    loss_kernel<<<1, 1>>>(out);
}

// round 5
// speedup vs baseline: 2.4633x; 1.7666x over previous
#include <cuda_runtime.h>
#include <math.h>
#include <stdint.h>

// ---------------- problem constants ----------------
#define SS   2048
#define BB   2
#define DD   768
#define HH   12
#define DHH  64
#define FF   3072
#define EE   8
#define TT   4096            // S*B
#define CAPN 1024            // capacity

// ---------------- device scratch ----------------
__device__ float g_qkv [(size_t)TT * 3 * DD];
__device__ float g_ctx [(size_t)TT * DD];
__device__ float g_attn[(size_t)TT * DD];
__device__ float g_x   [(size_t)TT * DD];
__device__ float g_buf [(size_t)EE * CAPN * DD];
__device__ float g_h   [(size_t)EE * CAPN * FF];
__device__ float g_y   [(size_t)EE * CAPN * DD];
__device__ int   g_eidx[TT];
__device__ int   g_pos [TT];
__device__ float g_gate[TT];
__device__ int   g_cnt    [EE];
__device__ int   g_cntfull[EE];
__device__ float g_probsum[EE];

// ---------------- helpers ----------------
__device__ __forceinline__ float to_tf32(float x) {
    uint32_t u;
    asm("cvt.rna.tf32.f32 %0, %1;" : "=r"(u) : "f"(x));
    return __uint_as_float(u);
}

__device__ __forceinline__ void mma_tf32(
    float& c0, float& c1, float& c2, float& c3,
    uint32_t a0, uint32_t a1, uint32_t a2, uint32_t a3,
    uint32_t b0, uint32_t b1)
{
    asm volatile(
        "mma.sync.aligned.m16n8k8.row.col.f32.tf32.tf32.f32 "
        "{%0,%1,%2,%3}, {%4,%5,%6,%7}, {%8,%9}, {%0,%1,%2,%3};"
        : "+f"(c0), "+f"(c1), "+f"(c2), "+f"(c3)
        : "r"(a0), "r"(a1), "r"(a2), "r"(a3), "r"(b0), "r"(b1));
}

// ---------------- zero accumulators ----------------
__global__ void zero_kernel() {
    if (threadIdx.x < EE) g_probsum[threadIdx.x] = 0.f;
}

// ======================================================================
// TF32 tensor-core GEMM (unchanged from passing R3 version).
// ======================================================================
template<int BLAYOUT, bool MOE>
__global__ __launch_bounds__(256) void gemm_tf32(
    const float* __restrict__ Aall, const float* __restrict__ Ball,
    const float* __restrict__ biasall, float* __restrict__ Call,
    int K, int N, int relu)
{
    __shared__ float As[128][36];
    __shared__ float Bs[32][136];

    const int tid  = threadIdx.x;
    const int lane = tid & 31;
    const int warp = tid >> 5;
    const int wm = (warp & 1) * 64;
    const int wn = (warp >> 1) * 32;

    const int n0 = blockIdx.x * 128;
    const int m0 = blockIdx.y * 128;

    const float* A; const float* B; const float* bias; float* C;
    int mlim;
    if (MOE) {
        int e = blockIdx.z;
        int m_e = g_cnt[e];
        if (m0 >= m_e) return;
        mlim = m_e;
        A    = Aall    + (size_t)e * CAPN * K;
        B    = Ball    + (size_t)e * K * N;
        bias = biasall + (size_t)e * N;
        C    = Call    + (size_t)e * CAPN * N;
    } else {
        mlim = 1 << 30;
        A = Aall; B = Ball; bias = biasall; C = Call;
    }

    const int ar = tid >> 1;
    const int ak = (tid & 1) * 16;
    const int bn_t = tid >> 1;
    const int bk_t = (tid & 1) * 16;
    const int bk_r = tid >> 3;
    const int bn_r = (tid & 7) * 16;

    float4 areg[4], breg[4];

    auto ldg_tile = [&](int k0) {
        const float* ap = A + (size_t)(m0 + ar) * K + k0 + ak;
        #pragma unroll
        for (int i = 0; i < 4; i++) areg[i] = *(const float4*)(ap + 4 * i);
        if (BLAYOUT == 1) {
            const float* bp = B + (size_t)(n0 + bn_t) * K + k0 + bk_t;
            #pragma unroll
            for (int i = 0; i < 4; i++) breg[i] = *(const float4*)(bp + 4 * i);
        } else {
            const float* bp = B + (size_t)(k0 + bk_r) * N + n0 + bn_r;
            #pragma unroll
            for (int i = 0; i < 4; i++) breg[i] = *(const float4*)(bp + 4 * i);
        }
    };

    auto sts_tile = [&]() {
        #pragma unroll
        for (int i = 0; i < 4; i++) {
            float* dst = &As[ar][ak + 4 * i];
            dst[0] = to_tf32(areg[i].x); dst[1] = to_tf32(areg[i].y);
            dst[2] = to_tf32(areg[i].z); dst[3] = to_tf32(areg[i].w);
        }
        if (BLAYOUT == 1) {
            #pragma unroll
            for (int i = 0; i < 4; i++) {
                Bs[bk_t + 4*i + 0][bn_t] = to_tf32(breg[i].x);
                Bs[bk_t + 4*i + 1][bn_t] = to_tf32(breg[i].y);
                Bs[bk_t + 4*i + 2][bn_t] = to_tf32(breg[i].z);
                Bs[bk_t + 4*i + 3][bn_t] = to_tf32(breg[i].w);
            }
        } else {
            #pragma unroll
            for (int i = 0; i < 4; i++) {
                float* dst = &Bs[bk_r][bn_r + 4 * i];
                dst[0] = to_tf32(breg[i].x); dst[1] = to_tf32(breg[i].y);
                dst[2] = to_tf32(breg[i].z); dst[3] = to_tf32(breg[i].w);
            }
        }
    };

    float acc[4][4][4];
    #pragma unroll
    for (int mi = 0; mi < 4; mi++)
        #pragma unroll
        for (int ni = 0; ni < 4; ni++)
            #pragma unroll
            for (int r = 0; r < 4; r++) acc[mi][ni][r] = 0.f;

    ldg_tile(0);
    sts_tile();
    __syncthreads();

    const int ntiles = K >> 5;
    for (int t = 0; t < ntiles; t++) {
        bool more = (t + 1 < ntiles);
        if (more) ldg_tile((t + 1) << 5);

        #pragma unroll
        for (int ks = 0; ks < 4; ks++) {
            uint32_t a[4][4], b[4][2];
            #pragma unroll
            for (int mi = 0; mi < 4; mi++) {
                int r = wm + mi * 16 + (lane >> 2);
                int c = ks * 8 + (lane & 3);
                a[mi][0] = __float_as_uint(As[r    ][c    ]);
                a[mi][1] = __float_as_uint(As[r + 8][c    ]);
                a[mi][2] = __float_as_uint(As[r    ][c + 4]);
                a[mi][3] = __float_as_uint(As[r + 8][c + 4]);
            }
            #pragma unroll
            for (int ni = 0; ni < 4; ni++) {
                int br = ks * 8 + (lane & 3);
                int bc = wn + ni * 8 + (lane >> 2);
                b[ni][0] = __float_as_uint(Bs[br    ][bc]);
                b[ni][1] = __float_as_uint(Bs[br + 4][bc]);
            }
            #pragma unroll
            for (int mi = 0; mi < 4; mi++)
                #pragma unroll
                for (int ni = 0; ni < 4; ni++)
                    mma_tf32(acc[mi][ni][0], acc[mi][ni][1],
                             acc[mi][ni][2], acc[mi][ni][3],
                             a[mi][0], a[mi][1], a[mi][2], a[mi][3],
                             b[ni][0], b[ni][1]);
        }
        __syncthreads();
        if (more) {
            sts_tile();
            __syncthreads();
        }
    }

    #pragma unroll
    for (int mi = 0; mi < 4; mi++) {
        int r0 = m0 + wm + mi * 16 + (lane >> 2);
        #pragma unroll
        for (int ni = 0; ni < 4; ni++) {
            int c = n0 + wn + ni * 8 + 2 * (lane & 3);
            float bx = bias[c], by = bias[c + 1];
            float v0 = acc[mi][ni][0] + bx, v1 = acc[mi][ni][1] + by;
            float v2 = acc[mi][ni][2] + bx, v3 = acc[mi][ni][3] + by;
            if (relu) {
                v0 = fmaxf(v0, 0.f); v1 = fmaxf(v1, 0.f);
                v2 = fmaxf(v2, 0.f); v3 = fmaxf(v3, 0.f);
            }
            if (r0 < mlim)     *(float2*)(C + (size_t)r0 * N + c)       = make_float2(v0, v1);
            if (r0 + 8 < mlim) *(float2*)(C + (size_t)(r0 + 8) * N + c) = make_float2(v2, v3);
        }
    }
}

// ======================================================================
// TF32 tensor-core flash attention.
// CTA: 128 queries, 8 warps x 16 query rows. KV tile = 32. grid (16, B*H).
// ======================================================================
#define ABR 128
#define ABC 32

__global__ __launch_bounds__(256) void attn_mma(
    const float* __restrict__ qkv, float* __restrict__ ctx)
{
    __shared__ float Ks[ABC][68];   // 68 % 32 == 4 -> conflict-free b-frags
    __shared__ float Vs[ABC][68];
    __shared__ float Ps[ABR][40];   // per-warp P slab (<=2-way conflicts)

    const int bh = blockIdx.y;
    const int b = bh / HH, h = bh % HH;
    const int q0 = blockIdx.x * ABR;
    const int tid = threadIdx.x, lane = tid & 31, warp = tid >> 5;
    const int wm = warp * 16;

    // ---- Q fragments (scale 1/8 folded in; exact power of 2) ----
    uint32_t qa[8][4];
    {
        int ra = q0 + wm + (lane >> 2);
        int rb = ra + 8;
        const float* pa = qkv + ((size_t)ra * BB + b) * (3 * DD) + h * DHH;
        const float* pb = qkv + ((size_t)rb * BB + b) * (3 * DD) + h * DHH;
        #pragma unroll
        for (int kk = 0; kk < 8; kk++) {
            int c = kk * 8 + (lane & 3);
            qa[kk][0] = __float_as_uint(to_tf32(pa[c    ] * 0.125f));
            qa[kk][1] = __float_as_uint(to_tf32(pb[c    ] * 0.125f));
            qa[kk][2] = __float_as_uint(to_tf32(pa[c + 4] * 0.125f));
            qa[kk][3] = __float_as_uint(to_tf32(pb[c + 4] * 0.125f));
        }
    }

    float m0 = -1e30f, m1 = -1e30f, l0 = 0.f, l1 = 0.f;
    float o[8][4];
    #pragma unroll
    for (int ni = 0; ni < 8; ni++)
        #pragma unroll
        for (int r = 0; r < 4; r++) o[ni][r] = 0.f;

    const int lr = tid >> 3;           // 0..31 kv row
    const int lc = (tid & 7) * 8;      // 0..56 dh col
    const int pra = wm + (lane >> 2);
    const int prb = pra + 8;
    const int pc  = 2 * (lane & 3);

    for (int kt = 0; kt < SS; kt += ABC) {
        // ---- stage K,V tile (tf32) ----
        const float* kr = qkv + ((size_t)(kt + lr) * BB + b) * (3 * DD) + DD + h * DHH + lc;
        float4 k1 = *(const float4*)(kr);
        float4 k2 = *(const float4*)(kr + 4);
        float4 v1 = *(const float4*)(kr + DD);
        float4 v2 = *(const float4*)(kr + DD + 4);
        Ks[lr][lc+0] = to_tf32(k1.x); Ks[lr][lc+1] = to_tf32(k1.y);
        Ks[lr][lc+2] = to_tf32(k1.z); Ks[lr][lc+3] = to_tf32(k1.w);
        Ks[lr][lc+4] = to_tf32(k2.x); Ks[lr][lc+5] = to_tf32(k2.y);
        Ks[lr][lc+6] = to_tf32(k2.z); Ks[lr][lc+7] = to_tf32(k2.w);
        Vs[lr][lc+0] = to_tf32(v1.x); Vs[lr][lc+1] = to_tf32(v1.y);
        Vs[lr][lc+2] = to_tf32(v1.z); Vs[lr][lc+3] = to_tf32(v1.w);
        Vs[lr][lc+4] = to_tf32(v2.x); Vs[lr][lc+5] = to_tf32(v2.y);
        Vs[lr][lc+6] = to_tf32(v2.z); Vs[lr][lc+7] = to_tf32(v2.w);
        __syncthreads();

        // ---- S = (Q/8) @ K^T : [16 x 32] per warp ----
        float s[4][4];
        #pragma unroll
        for (int ni = 0; ni < 4; ni++)
            #pragma unroll
            for (int r = 0; r < 4; r++) s[ni][r] = 0.f;

        #pragma unroll
        for (int kk = 0; kk < 8; kk++) {
            uint32_t kb[4][2];
            #pragma unroll
            for (int ni = 0; ni < 4; ni++) {
                kb[ni][0] = __float_as_uint(Ks[ni*8 + (lane>>2)][kk*8 + (lane&3)    ]);
                kb[ni][1] = __float_as_uint(Ks[ni*8 + (lane>>2)][kk*8 + (lane&3) + 4]);
            }
            #pragma unroll
            for (int ni = 0; ni < 4; ni++)
                mma_tf32(s[ni][0], s[ni][1], s[ni][2], s[ni][3],
                         qa[kk][0], qa[kk][1], qa[kk][2], qa[kk][3],
                         kb[ni][0], kb[ni][1]);
        }

        // ---- online softmax (rows: pra-local and +8) ----
        float mt0 = -1e30f, mt1 = -1e30f;
        #pragma unroll
        for (int ni = 0; ni < 4; ni++) {
            mt0 = fmaxf(mt0, fmaxf(s[ni][0], s[ni][1]));
            mt1 = fmaxf(mt1, fmaxf(s[ni][2], s[ni][3]));
        }
        mt0 = fmaxf(mt0, __shfl_xor_sync(0xffffffffu, mt0, 1));
        mt0 = fmaxf(mt0, __shfl_xor_sync(0xffffffffu, mt0, 2));
        mt1 = fmaxf(mt1, __shfl_xor_sync(0xffffffffu, mt1, 1));
        mt1 = fmaxf(mt1, __shfl_xor_sync(0xffffffffu, mt1, 2));
        float mn0 = fmaxf(m0, mt0), mn1 = fmaxf(m1, mt1);
        float f0 = __expf(m0 - mn0), f1 = __expf(m1 - mn1);
        m0 = mn0; m1 = mn1;
        l0 *= f0; l1 *= f1;
        #pragma unroll
        for (int ni = 0; ni < 8; ni++) {
            o[ni][0] *= f0; o[ni][1] *= f0;
            o[ni][2] *= f1; o[ni][3] *= f1;
        }

        float rs0 = 0.f, rs1 = 0.f;
        #pragma unroll
        for (int ni = 0; ni < 4; ni++) {
            float p00 = __expf(s[ni][0] - m0);
            float p01 = __expf(s[ni][1] - m0);
            float p10 = __expf(s[ni][2] - m1);
            float p11 = __expf(s[ni][3] - m1);
            rs0 += p00 + p01; rs1 += p10 + p11;
            Ps[pra][ni*8 + pc    ] = p00;
            Ps[pra][ni*8 + pc + 1] = p01;
            Ps[prb][ni*8 + pc    ] = p10;
            Ps[prb][ni*8 + pc + 1] = p11;
        }
        rs0 += __shfl_xor_sync(0xffffffffu, rs0, 1);
        rs0 += __shfl_xor_sync(0xffffffffu, rs0, 2);
        rs1 += __shfl_xor_sync(0xffffffffu, rs1, 1);
        rs1 += __shfl_xor_sync(0xffffffffu, rs1, 2);
        l0 += rs0; l1 += rs1;

        __syncwarp();   // warp-local P visibility (each warp reads only its rows)

        // ---- O += P @ V ----
        #pragma unroll
        for (int kk = 0; kk < 4; kk++) {
            uint32_t pfa[4];
            pfa[0] = __float_as_uint(to_tf32(Ps[pra][kk*8 + (lane&3)    ]));
            pfa[1] = __float_as_uint(to_tf32(Ps[prb][kk*8 + (lane&3)    ]));
            pfa[2] = __float_as_uint(to_tf32(Ps[pra][kk*8 + (lane&3) + 4]));
            pfa[3] = __float_as_uint(to_tf32(Ps[prb][kk*8 + (lane&3) + 4]));
            #pragma unroll
            for (int ni = 0; ni < 8; ni++) {
                uint32_t vb0 = __float_as_uint(Vs[kk*8 + (lane&3)    ][ni*8 + (lane>>2)]);
                uint32_t vb1 = __float_as_uint(Vs[kk*8 + (lane&3) + 4][ni*8 + (lane>>2)]);
                mma_tf32(o[ni][0], o[ni][1], o[ni][2], o[ni][3],
                         pfa[0], pfa[1], pfa[2], pfa[3], vb0, vb1);
            }
        }
        __syncthreads();   // protect Ks/Vs before next tile overwrite
    }

    // ---- epilogue ----
    float i0 = 1.f / l0, i1 = 1.f / l1;
    int ra = q0 + wm + (lane >> 2), rb = ra + 8;
    float* ca = ctx + ((size_t)ra * BB + b) * DD + h * DHH;
    float* cb = ctx + ((size_t)rb * BB + b) * DD + h * DHH;
    #pragma unroll
    for (int ni = 0; ni < 8; ni++) {
        int c = ni * 8 + pc;
        *(float2*)(ca + c) = make_float2(o[ni][0] * i0, o[ni][1] * i0);
        *(float2*)(cb + c) = make_float2(o[ni][2] * i1, o[ni][3] * i1);
    }
}

// ---------------- out = LayerNorm(a + b) ----------------
__global__ __launch_bounds__(256) void add_ln_kernel(
    const float* __restrict__ a, const float* __restrict__ bvec,
    const float* __restrict__ g, const float* __restrict__ beta,
    float* __restrict__ out)
{
    int t = blockIdx.x;
    __shared__ float row[DD];
    __shared__ float red[256];
    int tid = threadIdx.x;
    float s = 0.f;
    for (int d = tid; d < DD; d += 256) {
        float v = a[(size_t)t * DD + d] + bvec[(size_t)t * DD + d];
        row[d] = v; s += v;
    }
    red[tid] = s; __syncthreads();
    for (int o = 128; o > 0; o >>= 1) { if (tid < o) red[tid] += red[tid + o]; __syncthreads(); }
    float mean = red[0] * (1.f / DD);
    __syncthreads();
    float vs = 0.f;
    for (int d = tid; d < DD; d += 256) { float dv = row[d] - mean; vs += dv * dv; }
    red[tid] = vs; __syncthreads();
    for (int o = 128; o > 0; o >>= 1) { if (tid < o) red[tid] += red[tid + o]; __syncthreads(); }
    float rstd = rsqrtf(red[0] * (1.f / DD) + 1e-5f);
    for (int d = tid; d < DD; d += 256)
        out[(size_t)t * DD + d] = (row[d] - mean) * rstd * g[d] + beta[d];
}

// ---------------- router: warp per token ----------------
__global__ __launch_bounds__(256) void router_kernel(
    const float* __restrict__ x, const float* __restrict__ rw,
    const float* __restrict__ rb)
{
    int warp = threadIdx.x >> 5, lane = threadIdx.x & 31;
    int t = blockIdx.x * 8 + warp;
    __shared__ float sprob[EE];
    if (threadIdx.x < EE) sprob[threadIdx.x] = 0.f;
    __syncthreads();

    float pe[EE];
    #pragma unroll
    for (int e = 0; e < EE; e++) pe[e] = 0.f;
    const float* xr = x + (size_t)t * DD;
    for (int d = lane; d < DD; d += 32) {
        float xv = xr[d];
        #pragma unroll
        for (int e = 0; e < EE; e++) pe[e] += xv * rw[e * DD + d];
    }
    #pragma unroll
    for (int e = 0; e < EE; e++)
        #pragma unroll
        for (int o = 16; o > 0; o >>= 1) pe[e] += __shfl_xor_sync(0xffffffffu, pe[e], o);

    if (lane == 0) {
        float mx = -1e30f;
        #pragma unroll
        for (int e = 0; e < EE; e++) { pe[e] += rb[e]; mx = fmaxf(mx, pe[e]); }
        float p[EE]; float sum = 0.f;
        #pragma unroll
        for (int e = 0; e < EE; e++) { p[e] = __expf(pe[e] - mx); sum += p[e]; }
        float inv = 1.f / sum;
        int best = 0; float bp = -1.f;
        #pragma unroll
        for (int e = 0; e < EE; e++) { p[e] *= inv; }
        #pragma unroll
        for (int e = 0; e < EE; e++) { if (p[e] > bp) { bp = p[e]; best = e; } }
        g_eidx[t] = best; g_gate[t] = bp;
        #pragma unroll
        for (int e = 0; e < EE; e++) atomicAdd(&sprob[e], p[e]);
    }
    __syncthreads();
    if (threadIdx.x < EE) atomicAdd(&g_probsum[threadIdx.x], sprob[threadIdx.x]);
}

// ---------------- per-expert queue positions ----------------
__global__ void pos_kernel() {
    int warp = threadIdx.x >> 5, lane = threadIdx.x & 31;
    if (warp >= EE) return;
    int base = 0;
    for (int t0 = 0; t0 < TT; t0 += 32) {
        int t = t0 + lane;
        bool m = (g_eidx[t] == warp);
        unsigned msk = __ballot_sync(0xffffffffu, m);
        if (m) g_pos[t] = base + __popc(msk & ((1u << lane) - 1u));
        base += __popc(msk);
    }
    if (lane == 0) {
        g_cntfull[warp] = base;
        g_cnt[warp] = base < CAPN ? base : CAPN;
    }
}

// ---------------- gather tokens into expert buffers ----------------
__global__ __launch_bounds__(192) void gather_kernel(const float* __restrict__ x) {
    int t = blockIdx.x;
    int p = g_pos[t];
    if (p >= CAPN) return;
    int e = g_eidx[t];
    float4* dst = (float4*)(g_buf + ((size_t)e * CAPN + p) * DD);
    const float4* src = (const float4*)(x + (size_t)t * DD);
    dst[threadIdx.x] = src[threadIdx.x];
}

// ---------------- final: out = LN(x + gate * y[eidx,pos]) ----------------
__global__ __launch_bounds__(256) void final_kernel(
    const float* __restrict__ x, const float* __restrict__ g,
    const float* __restrict__ beta, float* __restrict__ out)
{
    int t = blockIdx.x;
    __shared__ float row[DD];
    __shared__ float red[256];
    int tid = threadIdx.x;
    int p = g_pos[t], e = g_eidx[t];
    float ga = g_gate[t];
    bool keep = (p < CAPN);
    const float* yrow = g_y + ((size_t)e * CAPN + (keep ? p : 0)) * DD;

    float s = 0.f;
    for (int d = tid; d < DD; d += 256) {
        float v = x[(size_t)t * DD + d] + (keep ? ga * yrow[d] : 0.f);
        row[d] = v; s += v;
    }
    red[tid] = s; __syncthreads();
    for (int o = 128; o > 0; o >>= 1) { if (tid < o) red[tid] += red[tid + o]; __syncthreads(); }
    float mean = red[0] * (1.f / DD);
    __syncthreads();
    float vs = 0.f;
    for (int d = tid; d < DD; d += 256) { float dv = row[d] - mean; vs += dv * dv; }
    red[tid] = vs; __syncthreads();
    for (int o = 128; o > 0; o >>= 1) { if (tid < o) red[tid] += red[tid + o]; __syncthreads(); }
    float rstd = rsqrtf(red[0] * (1.f / DD) + 1e-5f);
    for (int d = tid; d < DD; d += 256)
        out[(size_t)t * DD + d] = (row[d] - mean) * rstd * g[d] + beta[d];
}

// ---------------- lb loss ----------------
__global__ void loss_kernel(float* __restrict__ out) {
    float acc = 0.f;
    for (int e = 0; e < EE; e++)
        acc += ((float)g_cntfull[e] / (float)TT) * (g_probsum[e] / (float)TT);
    out[(size_t)TT * DD] = (float)EE * acc;
}

// ---------------- launch ----------------
extern "C" void kernel_launch(void* const* d_in, const int* in_sizes, int n_in,
                              void* d_out, int out_size)
{
    const float* src   = (const float*)d_in[0];
    const float* inw   = (const float*)d_in[1];
    const float* inb   = (const float*)d_in[2];
    const float* outw  = (const float*)d_in[3];
    const float* outb  = (const float*)d_in[4];
    const float* n1g   = (const float*)d_in[5];
    const float* n1b   = (const float*)d_in[6];
    const float* rw    = (const float*)d_in[7];
    const float* rb    = (const float*)d_in[8];
    const float* w1    = (const float*)d_in[9];
    const float* b1    = (const float*)d_in[10];
    const float* w2    = (const float*)d_in[11];
    const float* b2    = (const float*)d_in[12];
    const float* n2g   = (const float*)d_in[13];
    const float* n2b   = (const float*)d_in[14];
    float* out = (float*)d_out;

    float *p_qkv, *p_ctx, *p_attn, *p_x, *p_buf, *p_h, *p_y;
    cudaGetSymbolAddress((void**)&p_qkv,  g_qkv);
    cudaGetSymbolAddress((void**)&p_ctx,  g_ctx);
    cudaGetSymbolAddress((void**)&p_attn, g_attn);
    cudaGetSymbolAddress((void**)&p_x,    g_x);
    cudaGetSymbolAddress((void**)&p_buf,  g_buf);
    cudaGetSymbolAddress((void**)&p_h,    g_h);
    cudaGetSymbolAddress((void**)&p_y,    g_y);

    zero_kernel<<<1, 32>>>();

    // QKV = src @ in_proj_w^T + b
    gemm_tf32<1, false><<<dim3((3 * DD) / 128, TT / 128), 256>>>(
        src, inw, inb, p_qkv, DD, 3 * DD, 0);

    // attention -> ctx  (tensor-core flash)
    attn_mma<<<dim3(SS / ABR, BB * HH), 256>>>(p_qkv, p_ctx);

    // attn_out = ctx @ out_proj_w^T + b
    gemm_tf32<1, false><<<dim3(DD / 128, TT / 128), 256>>>(
        p_ctx, outw, outb, p_attn, DD, DD, 0);

    // x = LN(src + attn_out)
    add_ln_kernel<<<TT, 256>>>(src, p_attn, n1g, n1b, p_x);

    // routing
    router_kernel<<<TT / 8, 256>>>(p_x, rw, rb);
    pos_kernel<<<1, 256>>>();
    gather_kernel<<<TT, 192>>>(p_x);

    // expert FFN
    gemm_tf32<0, true><<<dim3(FF / 128, CAPN / 128, EE), 256>>>(
        p_buf, w1, b1, p_h, DD, FF, 1);
    gemm_tf32<0, true><<<dim3(DD / 128, CAPN / 128, EE), 256>>>(
        p_h, w2, b2, p_y, FF, DD, 0);

    // out = LN(x + gate*moe)
    final_kernel<<<TT, 256>>>(p_x, n2g, n2b, out);
    loss_kernel<<<1, 1>>>(out);
}

// round 6
// speedup vs baseline: 2.7651x; 1.1225x over previous
#include <cuda_runtime.h>
#include <math.h>
#include <stdint.h>

// ---------------- problem constants ----------------
#define SS   2048
#define BB   2
#define DD   768
#define HH   12
#define DHH  64
#define FF   3072
#define EE   8
#define TT   4096            // S*B
#define CAPN 1024            // capacity

// ---------------- device scratch ----------------
__device__ float g_qkv [(size_t)TT * 3 * DD];
__device__ float g_ctx [(size_t)TT * DD];
__device__ float g_attn[(size_t)TT * DD];
__device__ float g_x   [(size_t)TT * DD];
__device__ float g_buf [(size_t)EE * CAPN * DD];
__device__ float g_h   [(size_t)EE * CAPN * FF];
__device__ float g_y   [(size_t)EE * CAPN * DD];
__device__ int   g_eidx[TT];
__device__ int   g_pos [TT];
__device__ float g_gate[TT];
__device__ int   g_cnt    [EE];
__device__ int   g_cntfull[EE];
__device__ float g_probsum[EE];

// ---------------- helpers ----------------
__device__ __forceinline__ float to_tf32(float x) {
    uint32_t u;
    asm("cvt.rna.tf32.f32 %0, %1;" : "=r"(u) : "f"(x));
    return __uint_as_float(u);
}
__device__ __forceinline__ uint32_t to_tf32_u(float x) {
    uint32_t u;
    asm("cvt.rna.tf32.f32 %0, %1;" : "=r"(u) : "f"(x));
    return u;
}

__device__ __forceinline__ void mma_tf32(
    float& c0, float& c1, float& c2, float& c3,
    uint32_t a0, uint32_t a1, uint32_t a2, uint32_t a3,
    uint32_t b0, uint32_t b1)
{
    asm volatile(
        "mma.sync.aligned.m16n8k8.row.col.f32.tf32.tf32.f32 "
        "{%0,%1,%2,%3}, {%4,%5,%6,%7}, {%8,%9}, {%0,%1,%2,%3};"
        : "+f"(c0), "+f"(c1), "+f"(c2), "+f"(c3)
        : "r"(a0), "r"(a1), "r"(a2), "r"(a3), "r"(b0), "r"(b1));
}

__device__ __forceinline__ void cp16(float* dst, const float* src) {
    uint32_t d = (uint32_t)__cvta_generic_to_shared(dst);
    asm volatile("cp.async.cg.shared.global [%0], [%1], 16;" :: "r"(d), "l"(src));
}
__device__ __forceinline__ void cp_commit() {
    asm volatile("cp.async.commit_group;");
}
template<int N>
__device__ __forceinline__ void cp_wait() {
    asm volatile("cp.async.wait_group %0;" :: "n"(N));
}

// ---------------- zero accumulators ----------------
__global__ void zero_kernel() {
    if (threadIdx.x < EE) g_probsum[threadIdx.x] = 0.f;
}

// ======================================================================
// TF32 tensor-core GEMM, cp.async 2-stage pipeline, 2 CTAs/SM.
//   BLAYOUT=1: B given as Bt[N][K] (A @ Bt^T); B staged n-major [128][36]
//   BLAYOUT=0: B given as B[K][N]  (A @ B);    B staged k-major [32][136]
//   MOE=true : per-expert via blockIdx.z, dynamic M = g_cnt[e]
// Block tile 128x128, K-tile 32, 256 threads = 8 warps (2x4), warp 64x32.
// ======================================================================
#define ASTRIDE 36
#define ASZ     (128 * ASTRIDE)          // 4608 floats

template<int BLAYOUT, bool MOE>
__global__ __launch_bounds__(256, 2) void gemm_cp(
    const float* __restrict__ Aall, const float* __restrict__ Ball,
    const float* __restrict__ biasall, float* __restrict__ Call,
    int K, int N, int relu)
{
    constexpr int BSTRIDE = (BLAYOUT == 1) ? 36 : 136;
    constexpr int BSZ     = (BLAYOUT == 1) ? 128 * 36 : 32 * 136;
    constexpr int STAGE   = ASZ + BSZ;
    extern __shared__ float smem[];

    const int tid  = threadIdx.x;
    const int lane = tid & 31;
    const int warp = tid >> 5;
    const int wm = (warp & 1) * 64;
    const int wn = (warp >> 1) * 32;

    const int n0 = blockIdx.x * 128;
    const int m0 = blockIdx.y * 128;

    const float* A; const float* B; const float* bias; float* C;
    int mlim;
    if (MOE) {
        int e = blockIdx.z;
        int m_e = g_cnt[e];
        if (m0 >= m_e) return;
        mlim = m_e;
        A    = Aall    + (size_t)e * CAPN * K;
        B    = Ball    + (size_t)e * K * N;
        bias = biasall + (size_t)e * N;
        C    = Call    + (size_t)e * CAPN * N;
    } else {
        mlim = 1 << 30;
        A = Aall; B = Ball; bias = biasall; C = Call;
    }

    // staging mapping
    const int sr = tid >> 1;            // 0..127
    const int sk = (tid & 1) * 16;      // 0 / 16
    const int bkr = tid >> 3;           // 0..31  (BLAYOUT 0)
    const int bnc = (tid & 7) * 16;     // 0..112

    auto issue = [&](int k0, float* As, float* Bs) {
        const float* ap = A + (size_t)(m0 + sr) * K + k0 + sk;
        #pragma unroll
        for (int i = 0; i < 4; i++) cp16(&As[sr * ASTRIDE + sk + i * 4], ap + i * 4);
        if (BLAYOUT == 1) {
            const float* bp = B + (size_t)(n0 + sr) * K + k0 + sk;
            #pragma unroll
            for (int i = 0; i < 4; i++) cp16(&Bs[sr * BSTRIDE + sk + i * 4], bp + i * 4);
        } else {
            const float* bp = B + (size_t)(k0 + bkr) * N + n0 + bnc;
            #pragma unroll
            for (int i = 0; i < 4; i++) cp16(&Bs[bkr * BSTRIDE + bnc + i * 4], bp + i * 4);
        }
    };

    float acc[4][4][4];
    #pragma unroll
    for (int mi = 0; mi < 4; mi++)
        #pragma unroll
        for (int ni = 0; ni < 4; ni++)
            #pragma unroll
            for (int r = 0; r < 4; r++) acc[mi][ni][r] = 0.f;

    const int ntiles = K >> 5;

    issue(0, smem, smem + ASZ);
    cp_commit();
    issue(32, smem + STAGE, smem + STAGE + ASZ);
    cp_commit();

    const int afr = wm + (lane >> 2);      // a-frag row base
    const int afc = lane & 3;              // a-frag k base

    for (int t = 0; t < ntiles; t++) {
        float* As = smem + (t & 1) * STAGE;
        float* Bs = As + ASZ;

        if (t + 2 < ntiles) cp_wait<1>(); else cp_wait<0>();
        __syncthreads();

        #pragma unroll
        for (int ks = 0; ks < 4; ks++) {
            uint32_t a[4][4], b[4][2];
            const int c = ks * 8 + afc;
            #pragma unroll
            for (int mi = 0; mi < 4; mi++) {
                const float* p = &As[(afr + mi * 16) * ASTRIDE + c];
                a[mi][0] = to_tf32_u(p[0]);
                a[mi][1] = to_tf32_u(p[8 * ASTRIDE]);
                a[mi][2] = to_tf32_u(p[4]);
                a[mi][3] = to_tf32_u(p[8 * ASTRIDE + 4]);
            }
            if (BLAYOUT == 1) {
                #pragma unroll
                for (int ni = 0; ni < 4; ni++) {
                    const float* p = &Bs[(wn + ni * 8 + (lane >> 2)) * BSTRIDE + ks * 8 + afc];
                    b[ni][0] = to_tf32_u(p[0]);
                    b[ni][1] = to_tf32_u(p[4]);
                }
            } else {
                #pragma unroll
                for (int ni = 0; ni < 4; ni++) {
                    const float* p = &Bs[(ks * 8 + afc) * BSTRIDE + wn + ni * 8 + (lane >> 2)];
                    b[ni][0] = to_tf32_u(p[0]);
                    b[ni][1] = to_tf32_u(p[4 * BSTRIDE]);
                }
            }
            #pragma unroll
            for (int mi = 0; mi < 4; mi++)
                #pragma unroll
                for (int ni = 0; ni < 4; ni++)
                    mma_tf32(acc[mi][ni][0], acc[mi][ni][1],
                             acc[mi][ni][2], acc[mi][ni][3],
                             a[mi][0], a[mi][1], a[mi][2], a[mi][3],
                             b[ni][0], b[ni][1]);
        }
        __syncthreads();
        if (t + 2 < ntiles) {
            issue((t + 2) << 5, As, Bs);
            cp_commit();
        }
    }

    // ---- epilogue ----
    #pragma unroll
    for (int mi = 0; mi < 4; mi++) {
        int r0 = m0 + wm + mi * 16 + (lane >> 2);
        #pragma unroll
        for (int ni = 0; ni < 4; ni++) {
            int c = n0 + wn + ni * 8 + 2 * (lane & 3);
            float bx = bias[c], by = bias[c + 1];
            float v0 = acc[mi][ni][0] + bx, v1 = acc[mi][ni][1] + by;
            float v2 = acc[mi][ni][2] + bx, v3 = acc[mi][ni][3] + by;
            if (relu) {
                v0 = fmaxf(v0, 0.f); v1 = fmaxf(v1, 0.f);
                v2 = fmaxf(v2, 0.f); v3 = fmaxf(v3, 0.f);
            }
            if (r0 < mlim)     *(float2*)(C + (size_t)r0 * N + c)       = make_float2(v0, v1);
            if (r0 + 8 < mlim) *(float2*)(C + (size_t)(r0 + 8) * N + c) = make_float2(v2, v3);
        }
    }
}

// ======================================================================
// TF32 tensor-core flash attention (unchanged from R4 passing version).
// ======================================================================
#define ABR 128
#define ABC 32

__global__ __launch_bounds__(256) void attn_mma(
    const float* __restrict__ qkv, float* __restrict__ ctx)
{
    __shared__ float Ks[ABC][68];
    __shared__ float Vs[ABC][68];
    __shared__ float Ps[ABR][40];

    const int bh = blockIdx.y;
    const int b = bh / HH, h = bh % HH;
    const int q0 = blockIdx.x * ABR;
    const int tid = threadIdx.x, lane = tid & 31, warp = tid >> 5;
    const int wm = warp * 16;

    uint32_t qa[8][4];
    {
        int ra = q0 + wm + (lane >> 2);
        int rb = ra + 8;
        const float* pa = qkv + ((size_t)ra * BB + b) * (3 * DD) + h * DHH;
        const float* pb = qkv + ((size_t)rb * BB + b) * (3 * DD) + h * DHH;
        #pragma unroll
        for (int kk = 0; kk < 8; kk++) {
            int c = kk * 8 + (lane & 3);
            qa[kk][0] = __float_as_uint(to_tf32(pa[c    ] * 0.125f));
            qa[kk][1] = __float_as_uint(to_tf32(pb[c    ] * 0.125f));
            qa[kk][2] = __float_as_uint(to_tf32(pa[c + 4] * 0.125f));
            qa[kk][3] = __float_as_uint(to_tf32(pb[c + 4] * 0.125f));
        }
    }

    float m0 = -1e30f, m1 = -1e30f, l0 = 0.f, l1 = 0.f;
    float o[8][4];
    #pragma unroll
    for (int ni = 0; ni < 8; ni++)
        #pragma unroll
        for (int r = 0; r < 4; r++) o[ni][r] = 0.f;

    const int lr = tid >> 3;
    const int lc = (tid & 7) * 8;
    const int pra = wm + (lane >> 2);
    const int prb = pra + 8;
    const int pc  = 2 * (lane & 3);

    for (int kt = 0; kt < SS; kt += ABC) {
        const float* kr = qkv + ((size_t)(kt + lr) * BB + b) * (3 * DD) + DD + h * DHH + lc;
        float4 k1 = *(const float4*)(kr);
        float4 k2 = *(const float4*)(kr + 4);
        float4 v1 = *(const float4*)(kr + DD);
        float4 v2 = *(const float4*)(kr + DD + 4);
        Ks[lr][lc+0] = to_tf32(k1.x); Ks[lr][lc+1] = to_tf32(k1.y);
        Ks[lr][lc+2] = to_tf32(k1.z); Ks[lr][lc+3] = to_tf32(k1.w);
        Ks[lr][lc+4] = to_tf32(k2.x); Ks[lr][lc+5] = to_tf32(k2.y);
        Ks[lr][lc+6] = to_tf32(k2.z); Ks[lr][lc+7] = to_tf32(k2.w);
        Vs[lr][lc+0] = to_tf32(v1.x); Vs[lr][lc+1] = to_tf32(v1.y);
        Vs[lr][lc+2] = to_tf32(v1.z); Vs[lr][lc+3] = to_tf32(v1.w);
        Vs[lr][lc+4] = to_tf32(v2.x); Vs[lr][lc+5] = to_tf32(v2.y);
        Vs[lr][lc+6] = to_tf32(v2.z); Vs[lr][lc+7] = to_tf32(v2.w);
        __syncthreads();

        float s[4][4];
        #pragma unroll
        for (int ni = 0; ni < 4; ni++)
            #pragma unroll
            for (int r = 0; r < 4; r++) s[ni][r] = 0.f;

        #pragma unroll
        for (int kk = 0; kk < 8; kk++) {
            uint32_t kb[4][2];
            #pragma unroll
            for (int ni = 0; ni < 4; ni++) {
                kb[ni][0] = __float_as_uint(Ks[ni*8 + (lane>>2)][kk*8 + (lane&3)    ]);
                kb[ni][1] = __float_as_uint(Ks[ni*8 + (lane>>2)][kk*8 + (lane&3) + 4]);
            }
            #pragma unroll
            for (int ni = 0; ni < 4; ni++)
                mma_tf32(s[ni][0], s[ni][1], s[ni][2], s[ni][3],
                         qa[kk][0], qa[kk][1], qa[kk][2], qa[kk][3],
                         kb[ni][0], kb[ni][1]);
        }

        float mt0 = -1e30f, mt1 = -1e30f;
        #pragma unroll
        for (int ni = 0; ni < 4; ni++) {
            mt0 = fmaxf(mt0, fmaxf(s[ni][0], s[ni][1]));
            mt1 = fmaxf(mt1, fmaxf(s[ni][2], s[ni][3]));
        }
        mt0 = fmaxf(mt0, __shfl_xor_sync(0xffffffffu, mt0, 1));
        mt0 = fmaxf(mt0, __shfl_xor_sync(0xffffffffu, mt0, 2));
        mt1 = fmaxf(mt1, __shfl_xor_sync(0xffffffffu, mt1, 1));
        mt1 = fmaxf(mt1, __shfl_xor_sync(0xffffffffu, mt1, 2));
        float mn0 = fmaxf(m0, mt0), mn1 = fmaxf(m1, mt1);
        float f0 = __expf(m0 - mn0), f1 = __expf(m1 - mn1);
        m0 = mn0; m1 = mn1;
        l0 *= f0; l1 *= f1;
        #pragma unroll
        for (int ni = 0; ni < 8; ni++) {
            o[ni][0] *= f0; o[ni][1] *= f0;
            o[ni][2] *= f1; o[ni][3] *= f1;
        }

        float rs0 = 0.f, rs1 = 0.f;
        #pragma unroll
        for (int ni = 0; ni < 4; ni++) {
            float p00 = __expf(s[ni][0] - m0);
            float p01 = __expf(s[ni][1] - m0);
            float p10 = __expf(s[ni][2] - m1);
            float p11 = __expf(s[ni][3] - m1);
            rs0 += p00 + p01; rs1 += p10 + p11;
            Ps[pra][ni*8 + pc    ] = p00;
            Ps[pra][ni*8 + pc + 1] = p01;
            Ps[prb][ni*8 + pc    ] = p10;
            Ps[prb][ni*8 + pc + 1] = p11;
        }
        rs0 += __shfl_xor_sync(0xffffffffu, rs0, 1);
        rs0 += __shfl_xor_sync(0xffffffffu, rs0, 2);
        rs1 += __shfl_xor_sync(0xffffffffu, rs1, 1);
        rs1 += __shfl_xor_sync(0xffffffffu, rs1, 2);
        l0 += rs0; l1 += rs1;

        __syncwarp();

        #pragma unroll
        for (int kk = 0; kk < 4; kk++) {
            uint32_t pfa[4];
            pfa[0] = __float_as_uint(to_tf32(Ps[pra][kk*8 + (lane&3)    ]));
            pfa[1] = __float_as_uint(to_tf32(Ps[prb][kk*8 + (lane&3)    ]));
            pfa[2] = __float_as_uint(to_tf32(Ps[pra][kk*8 + (lane&3) + 4]));
            pfa[3] = __float_as_uint(to_tf32(Ps[prb][kk*8 + (lane&3) + 4]));
            #pragma unroll
            for (int ni = 0; ni < 8; ni++) {
                uint32_t vb0 = __float_as_uint(Vs[kk*8 + (lane&3)    ][ni*8 + (lane>>2)]);
                uint32_t vb1 = __float_as_uint(Vs[kk*8 + (lane&3) + 4][ni*8 + (lane>>2)]);
                mma_tf32(o[ni][0], o[ni][1], o[ni][2], o[ni][3],
                         pfa[0], pfa[1], pfa[2], pfa[3], vb0, vb1);
            }
        }
        __syncthreads();
    }

    float i0 = 1.f / l0, i1 = 1.f / l1;
    int ra = q0 + wm + (lane >> 2), rb = ra + 8;
    float* ca = ctx + ((size_t)ra * BB + b) * DD + h * DHH;
    float* cb = ctx + ((size_t)rb * BB + b) * DD + h * DHH;
    #pragma unroll
    for (int ni = 0; ni < 8; ni++) {
        int c = ni * 8 + pc;
        *(float2*)(ca + c) = make_float2(o[ni][0] * i0, o[ni][1] * i0);
        *(float2*)(cb + c) = make_float2(o[ni][2] * i1, o[ni][3] * i1);
    }
}

// ---------------- out = LayerNorm(a + b) ----------------
__global__ __launch_bounds__(256) void add_ln_kernel(
    const float* __restrict__ a, const float* __restrict__ bvec,
    const float* __restrict__ g, const float* __restrict__ beta,
    float* __restrict__ out)
{
    int t = blockIdx.x;
    __shared__ float row[DD];
    __shared__ float red[256];
    int tid = threadIdx.x;
    float s = 0.f;
    for (int d = tid; d < DD; d += 256) {
        float v = a[(size_t)t * DD + d] + bvec[(size_t)t * DD + d];
        row[d] = v; s += v;
    }
    red[tid] = s; __syncthreads();
    for (int o = 128; o > 0; o >>= 1) { if (tid < o) red[tid] += red[tid + o]; __syncthreads(); }
    float mean = red[0] * (1.f / DD);
    __syncthreads();
    float vs = 0.f;
    for (int d = tid; d < DD; d += 256) { float dv = row[d] - mean; vs += dv * dv; }
    red[tid] = vs; __syncthreads();
    for (int o = 128; o > 0; o >>= 1) { if (tid < o) red[tid] += red[tid + o]; __syncthreads(); }
    float rstd = rsqrtf(red[0] * (1.f / DD) + 1e-5f);
    for (int d = tid; d < DD; d += 256)
        out[(size_t)t * DD + d] = (row[d] - mean) * rstd * g[d] + beta[d];
}

// ---------------- router: warp per token ----------------
__global__ __launch_bounds__(256) void router_kernel(
    const float* __restrict__ x, const float* __restrict__ rw,
    const float* __restrict__ rb)
{
    int warp = threadIdx.x >> 5, lane = threadIdx.x & 31;
    int t = blockIdx.x * 8 + warp;
    __shared__ float sprob[EE];
    if (threadIdx.x < EE) sprob[threadIdx.x] = 0.f;
    __syncthreads();

    float pe[EE];
    #pragma unroll
    for (int e = 0; e < EE; e++) pe[e] = 0.f;
    const float* xr = x + (size_t)t * DD;
    for (int d = lane; d < DD; d += 32) {
        float xv = xr[d];
        #pragma unroll
        for (int e = 0; e < EE; e++) pe[e] += xv * rw[e * DD + d];
    }
    #pragma unroll
    for (int e = 0; e < EE; e++)
        #pragma unroll
        for (int o = 16; o > 0; o >>= 1) pe[e] += __shfl_xor_sync(0xffffffffu, pe[e], o);

    if (lane == 0) {
        float mx = -1e30f;
        #pragma unroll
        for (int e = 0; e < EE; e++) { pe[e] += rb[e]; mx = fmaxf(mx, pe[e]); }
        float p[EE]; float sum = 0.f;
        #pragma unroll
        for (int e = 0; e < EE; e++) { p[e] = __expf(pe[e] - mx); sum += p[e]; }
        float inv = 1.f / sum;
        int best = 0; float bp = -1.f;
        #pragma unroll
        for (int e = 0; e < EE; e++) { p[e] *= inv; }
        #pragma unroll
        for (int e = 0; e < EE; e++) { if (p[e] > bp) { bp = p[e]; best = e; } }
        g_eidx[t] = best; g_gate[t] = bp;
        #pragma unroll
        for (int e = 0; e < EE; e++) atomicAdd(&sprob[e], p[e]);
    }
    __syncthreads();
    if (threadIdx.x < EE) atomicAdd(&g_probsum[threadIdx.x], sprob[threadIdx.x]);
}

// ---------------- per-expert queue positions ----------------
__global__ void pos_kernel() {
    int warp = threadIdx.x >> 5, lane = threadIdx.x & 31;
    if (warp >= EE) return;
    int base = 0;
    for (int t0 = 0; t0 < TT; t0 += 32) {
        int t = t0 + lane;
        bool m = (g_eidx[t] == warp);
        unsigned msk = __ballot_sync(0xffffffffu, m);
        if (m) g_pos[t] = base + __popc(msk & ((1u << lane) - 1u));
        base += __popc(msk);
    }
    if (lane == 0) {
        g_cntfull[warp] = base;
        g_cnt[warp] = base < CAPN ? base : CAPN;
    }
}

// ---------------- gather tokens into expert buffers ----------------
__global__ __launch_bounds__(192) void gather_kernel(const float* __restrict__ x) {
    int t = blockIdx.x;
    int p = g_pos[t];
    if (p >= CAPN) return;
    int e = g_eidx[t];
    float4* dst = (float4*)(g_buf + ((size_t)e * CAPN + p) * DD);
    const float4* src = (const float4*)(x + (size_t)t * DD);
    dst[threadIdx.x] = src[threadIdx.x];
}

// ---------------- final: out = LN(x + gate * y[eidx,pos]) ----------------
__global__ __launch_bounds__(256) void final_kernel(
    const float* __restrict__ x, const float* __restrict__ g,
    const float* __restrict__ beta, float* __restrict__ out)
{
    int t = blockIdx.x;
    __shared__ float row[DD];
    __shared__ float red[256];
    int tid = threadIdx.x;
    int p = g_pos[t], e = g_eidx[t];
    float ga = g_gate[t];
    bool keep = (p < CAPN);
    const float* yrow = g_y + ((size_t)e * CAPN + (keep ? p : 0)) * DD;

    float s = 0.f;
    for (int d = tid; d < DD; d += 256) {
        float v = x[(size_t)t * DD + d] + (keep ? ga * yrow[d] : 0.f);
        row[d] = v; s += v;
    }
    red[tid] = s; __syncthreads();
    for (int o = 128; o > 0; o >>= 1) { if (tid < o) red[tid] += red[tid + o]; __syncthreads(); }
    float mean = red[0] * (1.f / DD);
    __syncthreads();
    float vs = 0.f;
    for (int d = tid; d < DD; d += 256) { float dv = row[d] - mean; vs += dv * dv; }
    red[tid] = vs; __syncthreads();
    for (int o = 128; o > 0; o >>= 1) { if (tid < o) red[tid] += red[tid + o]; __syncthreads(); }
    float rstd = rsqrtf(red[0] * (1.f / DD) + 1e-5f);
    for (int d = tid; d < DD; d += 256)
        out[(size_t)t * DD + d] = (row[d] - mean) * rstd * g[d] + beta[d];
}

// ---------------- lb loss ----------------
__global__ void loss_kernel(float* __restrict__ out) {
    float acc = 0.f;
    for (int e = 0; e < EE; e++)
        acc += ((float)g_cntfull[e] / (float)TT) * (g_probsum[e] / (float)TT);
    out[(size_t)TT * DD] = (float)EE * acc;
}

// ---------------- launch ----------------
extern "C" void kernel_launch(void* const* d_in, const int* in_sizes, int n_in,
                              void* d_out, int out_size)
{
    const float* src   = (const float*)d_in[0];
    const float* inw   = (const float*)d_in[1];
    const float* inb   = (const float*)d_in[2];
    const float* outw  = (const float*)d_in[3];
    const float* outb  = (const float*)d_in[4];
    const float* n1g   = (const float*)d_in[5];
    const float* n1b   = (const float*)d_in[6];
    const float* rw    = (const float*)d_in[7];
    const float* rb    = (const float*)d_in[8];
    const float* w1    = (const float*)d_in[9];
    const float* b1    = (const float*)d_in[10];
    const float* w2    = (const float*)d_in[11];
    const float* b2    = (const float*)d_in[12];
    const float* n2g   = (const float*)d_in[13];
    const float* n2b   = (const float*)d_in[14];
    float* out = (float*)d_out;

    float *p_qkv, *p_ctx, *p_attn, *p_x, *p_buf, *p_h, *p_y;
    cudaGetSymbolAddress((void**)&p_qkv,  g_qkv);
    cudaGetSymbolAddress((void**)&p_ctx,  g_ctx);
    cudaGetSymbolAddress((void**)&p_attn, g_attn);
    cudaGetSymbolAddress((void**)&p_x,    g_x);
    cudaGetSymbolAddress((void**)&p_buf,  g_buf);
    cudaGetSymbolAddress((void**)&p_h,    g_h);
    cudaGetSymbolAddress((void**)&p_y,    g_y);

    // dynamic SMEM sizes: 2 stages of (A tile + B tile)
    const int smem_bt  = 2 * (ASZ + 128 * 36) * 4;   // BLAYOUT=1: 73728 B
    const int smem_kn  = 2 * (ASZ + 32 * 136) * 4;   // BLAYOUT=0: 71680 B
    cudaFuncSetAttribute(gemm_cp<1, false>,
                         cudaFuncAttributeMaxDynamicSharedMemorySize, smem_bt);
    cudaFuncSetAttribute(gemm_cp<0, true>,
                         cudaFuncAttributeMaxDynamicSharedMemorySize, smem_kn);

    zero_kernel<<<1, 32>>>();

    // QKV = src @ in_proj_w^T + b
    gemm_cp<1, false><<<dim3((3 * DD) / 128, TT / 128), 256, smem_bt>>>(
        src, inw, inb, p_qkv, DD, 3 * DD, 0);

    // attention -> ctx  (tensor-core flash)
    attn_mma<<<dim3(SS / ABR, BB * HH), 256>>>(p_qkv, p_ctx);

    // attn_out = ctx @ out_proj_w^T + b
    gemm_cp<1, false><<<dim3(DD / 128, TT / 128), 256, smem_bt>>>(
        p_ctx, outw, outb, p_attn, DD, DD, 0);

    // x = LN(src + attn_out)
    add_ln_kernel<<<TT, 256>>>(src, p_attn, n1g, n1b, p_x);

    // routing
    router_kernel<<<TT / 8, 256>>>(p_x, rw, rb);
    pos_kernel<<<1, 256>>>();
    gather_kernel<<<TT, 192>>>(p_x);

    // expert FFN
    gemm_cp<0, true><<<dim3(FF / 128, CAPN / 128, EE), 256, smem_kn>>>(
        p_buf, w1, b1, p_h, DD, FF, 1);
    gemm_cp<0, true><<<dim3(DD / 128, CAPN / 128, EE), 256, smem_kn>>>(
        p_h, w2, b2, p_y, FF, DD, 0);

    // out = LN(x + gate*moe)
    final_kernel<<<TT, 256>>>(p_x, n2g, n2b, out);
    loss_kernel<<<1, 1>>>(out);
}

// round 7
// speedup vs baseline: 3.5310x; 1.2770x over previous
#include <cuda_runtime.h>
#include <cuda_bf16.h>
#include <math.h>
#include <stdint.h>

// ---------------- problem constants ----------------
#define SS   2048
#define BB   2
#define DD   768
#define HH   12
#define DHH  64
#define FF   3072
#define EE   8
#define TT   4096            // S*B
#define CAPN 1024            // capacity

// ---------------- device scratch ----------------
__device__ float g_qkv [(size_t)TT * 3 * DD];
__device__ float g_ctx [(size_t)TT * DD];
__device__ float g_attn[(size_t)TT * DD];
__device__ float g_x   [(size_t)TT * DD];
__device__ float g_y   [(size_t)EE * CAPN * DD];
__device__ __nv_bfloat16 g_bufb[(size_t)EE * CAPN * DD];
__device__ __nv_bfloat16 g_hb  [(size_t)EE * CAPN * FF];
__device__ __nv_bfloat16 g_w1b [(size_t)EE * DD * FF];   // [e][F][D] n-major
__device__ __nv_bfloat16 g_w2b [(size_t)EE * DD * FF];   // [e][D][F] n-major
__device__ int   g_eidx[TT];
__device__ int   g_pos [TT];
__device__ float g_gate[TT];
__device__ int   g_cnt    [EE];
__device__ int   g_cntfull[EE];
__device__ float g_probsum[EE];

// ---------------- helpers ----------------
__device__ __forceinline__ float to_tf32(float x) {
    uint32_t u;
    asm("cvt.rna.tf32.f32 %0, %1;" : "=r"(u) : "f"(x));
    return __uint_as_float(u);
}
__device__ __forceinline__ uint32_t to_tf32_u(float x) {
    uint32_t u;
    asm("cvt.rna.tf32.f32 %0, %1;" : "=r"(u) : "f"(x));
    return u;
}

__device__ __forceinline__ void mma_tf32(
    float& c0, float& c1, float& c2, float& c3,
    uint32_t a0, uint32_t a1, uint32_t a2, uint32_t a3,
    uint32_t b0, uint32_t b1)
{
    asm volatile(
        "mma.sync.aligned.m16n8k8.row.col.f32.tf32.tf32.f32 "
        "{%0,%1,%2,%3}, {%4,%5,%6,%7}, {%8,%9}, {%0,%1,%2,%3};"
        : "+f"(c0), "+f"(c1), "+f"(c2), "+f"(c3)
        : "r"(a0), "r"(a1), "r"(a2), "r"(a3), "r"(b0), "r"(b1));
}

__device__ __forceinline__ void mma_bf16(
    float& c0, float& c1, float& c2, float& c3,
    uint32_t a0, uint32_t a1, uint32_t a2, uint32_t a3,
    uint32_t b0, uint32_t b1)
{
    asm volatile(
        "mma.sync.aligned.m16n8k16.row.col.f32.bf16.bf16.f32 "
        "{%0,%1,%2,%3}, {%4,%5,%6,%7}, {%8,%9}, {%0,%1,%2,%3};"
        : "+f"(c0), "+f"(c1), "+f"(c2), "+f"(c3)
        : "r"(a0), "r"(a1), "r"(a2), "r"(a3), "r"(b0), "r"(b1));
}

__device__ __forceinline__ void cp16(void* dst, const void* src) {
    uint32_t d = (uint32_t)__cvta_generic_to_shared(dst);
    asm volatile("cp.async.cg.shared.global [%0], [%1], 16;" :: "r"(d), "l"(src));
}
__device__ __forceinline__ void cp_commit() {
    asm volatile("cp.async.commit_group;");
}
template<int N>
__device__ __forceinline__ void cp_wait() {
    asm volatile("cp.async.wait_group %0;" :: "n"(N));
}

// ---------------- zero accumulators ----------------
__global__ void zero_kernel() {
    if (threadIdx.x < EE) g_probsum[threadIdx.x] = 0.f;
}

// ---------------- tiled transpose + fp32->bf16 convert ----------------
// in[e][R][C] fp32  ->  out[e][C][R] bf16.   grid (C/32, R/32, E), block (32,8)
__global__ __launch_bounds__(256) void convert_t(
    const float* __restrict__ in, __nv_bfloat16* __restrict__ out, int R, int C)
{
    __shared__ float tile[32][33];
    int e = blockIdx.z;
    int c0 = blockIdx.x * 32, r0 = blockIdx.y * 32;
    const float* ip = in + (size_t)e * R * C;
    __nv_bfloat16* op = out + (size_t)e * R * C;
    int tx = threadIdx.x, ty = threadIdx.y;
    #pragma unroll
    for (int j = 0; j < 4; j++)
        tile[ty + j * 8][tx] = ip[(size_t)(r0 + ty + j * 8) * C + c0 + tx];
    __syncthreads();
    #pragma unroll
    for (int j = 0; j < 4; j++)
        op[(size_t)(c0 + ty + j * 8) * R + r0 + tx] = __float2bfloat16(tile[tx][ty + j * 8]);
}

// ======================================================================
// TF32 GEMM: C[M,N] = A[M,K] @ Bt[N,K]^T + bias. 3-stage cp.async, 1 sync/tile.
// Arithmetic order identical to prior rounds (bitwise-stable x -> routing safe).
// ======================================================================
#define ASTRIDE 36
#define ASZ     (128 * ASTRIDE)          // 4608 floats
#define TSTAGE  (2 * ASZ)                // A + B (both 128x36)

__global__ __launch_bounds__(256, 2) void gemm_tf32_bt(
    const float* __restrict__ A, const float* __restrict__ B,
    const float* __restrict__ bias, float* __restrict__ C,
    int K, int N)
{
    extern __shared__ float smem[];

    const int tid  = threadIdx.x;
    const int lane = tid & 31;
    const int warp = tid >> 5;
    const int wm = (warp & 1) * 64;
    const int wn = (warp >> 1) * 32;
    const int n0 = blockIdx.x * 128;
    const int m0 = blockIdx.y * 128;

    const int sr = tid >> 1;
    const int sk = (tid & 1) * 16;

    auto issue = [&](int k0, float* As) {
        float* Bs = As + ASZ;
        const float* ap = A + (size_t)(m0 + sr) * K + k0 + sk;
        #pragma unroll
        for (int i = 0; i < 4; i++) cp16(&As[sr * ASTRIDE + sk + i * 4], ap + i * 4);
        const float* bp = B + (size_t)(n0 + sr) * K + k0 + sk;
        #pragma unroll
        for (int i = 0; i < 4; i++) cp16(&Bs[sr * ASTRIDE + sk + i * 4], bp + i * 4);
    };

    float acc[4][4][4];
    #pragma unroll
    for (int mi = 0; mi < 4; mi++)
        #pragma unroll
        for (int ni = 0; ni < 4; ni++)
            #pragma unroll
            for (int r = 0; r < 4; r++) acc[mi][ni][r] = 0.f;

    const int ntiles = K >> 5;
    issue(0, smem);           cp_commit();
    issue(32, smem + TSTAGE); cp_commit();

    const int afr = wm + (lane >> 2);
    const int afc = lane & 3;

    int sidx = 0;
    for (int t = 0; t < ntiles; t++) {
        float* As = smem + sidx * TSTAGE;
        float* Bs = As + ASZ;

        if (t + 1 < ntiles) cp_wait<1>(); else cp_wait<0>();
        __syncthreads();

        #pragma unroll
        for (int ks = 0; ks < 4; ks++) {
            uint32_t a[4][4], b[4][2];
            const int c = ks * 8 + afc;
            #pragma unroll
            for (int mi = 0; mi < 4; mi++) {
                const float* p = &As[(afr + mi * 16) * ASTRIDE + c];
                a[mi][0] = to_tf32_u(p[0]);
                a[mi][1] = to_tf32_u(p[8 * ASTRIDE]);
                a[mi][2] = to_tf32_u(p[4]);
                a[mi][3] = to_tf32_u(p[8 * ASTRIDE + 4]);
            }
            #pragma unroll
            for (int ni = 0; ni < 4; ni++) {
                const float* p = &Bs[(wn + ni * 8 + (lane >> 2)) * ASTRIDE + c];
                b[ni][0] = to_tf32_u(p[0]);
                b[ni][1] = to_tf32_u(p[4]);
            }
            #pragma unroll
            for (int mi = 0; mi < 4; mi++)
                #pragma unroll
                for (int ni = 0; ni < 4; ni++)
                    mma_tf32(acc[mi][ni][0], acc[mi][ni][1],
                             acc[mi][ni][2], acc[mi][ni][3],
                             a[mi][0], a[mi][1], a[mi][2], a[mi][3],
                             b[ni][0], b[ni][1]);
        }

        if (t + 2 < ntiles) {
            int widx = sidx + 2; if (widx >= 3) widx -= 3;
            issue((t + 2) << 5, smem + widx * TSTAGE);
            cp_commit();
        }
        if (++sidx == 3) sidx = 0;
    }

    #pragma unroll
    for (int mi = 0; mi < 4; mi++) {
        int r0 = m0 + wm + mi * 16 + (lane >> 2);
        #pragma unroll
        for (int ni = 0; ni < 4; ni++) {
            int c = n0 + wn + ni * 8 + 2 * (lane & 3);
            float bx = bias[c], by = bias[c + 1];
            *(float2*)(C + (size_t)r0 * N + c)       = make_float2(acc[mi][ni][0] + bx, acc[mi][ni][1] + by);
            *(float2*)(C + (size_t)(r0 + 8) * N + c) = make_float2(acc[mi][ni][2] + bx, acc[mi][ni][3] + by);
        }
    }
}

// ======================================================================
// BF16 MoE GEMM: per-expert C = A @ B^T(n-major) + bias.
// A bf16 [CAP][K] row-major, B bf16 [N][K] n-major. 4-stage cp.async.
// Block tile 128x128x32, m16n8k16. OUTBF: write bf16 (gemm1->h), else fp32.
// ======================================================================
#define BFSTR   40                        // bf16 row stride (20 words)
#define BFW     20                        // words per row
#define BFTILEW (128 * BFW)               // 2560 words per tile
#define BFSTAGE (2 * BFTILEW)             // A + B

template<bool OUTBF>
__global__ __launch_bounds__(256, 2) void gemm_bf16_moe(
    const __nv_bfloat16* __restrict__ Aall, const __nv_bfloat16* __restrict__ Ball,
    const float* __restrict__ biasall, void* __restrict__ Call,
    int K, int N, int relu)
{
    extern __shared__ float smem[];
    uint32_t* W = (uint32_t*)smem;

    const int tid  = threadIdx.x;
    const int lane = tid & 31;
    const int warp = tid >> 5;
    const int wm = (warp & 1) * 64;
    const int wn = (warp >> 1) * 32;
    const int n0 = blockIdx.x * 128;
    const int m0 = blockIdx.y * 128;

    const int e = blockIdx.z;
    const int mlim = g_cnt[e];
    if (m0 >= mlim) return;
    const __nv_bfloat16* A = Aall + (size_t)e * CAPN * K;
    const __nv_bfloat16* B = Ball + (size_t)e * (size_t)N * K;
    const float* bias = biasall + (size_t)e * N;

    const int sr = tid >> 1;            // 0..127
    const int sk = (tid & 1) * 16;      // 0 / 16 (bf16 elems)

    auto issue = [&](int k0, int stage) {
        __nv_bfloat16* As = (__nv_bfloat16*)(W + stage * BFSTAGE);
        __nv_bfloat16* Bs = (__nv_bfloat16*)(W + stage * BFSTAGE + BFTILEW);
        const __nv_bfloat16* ap = A + (size_t)(m0 + sr) * K + k0 + sk;
        cp16(&As[sr * BFSTR + sk], ap);
        cp16(&As[sr * BFSTR + sk + 8], ap + 8);
        const __nv_bfloat16* bp = B + (size_t)(n0 + sr) * K + k0 + sk;
        cp16(&Bs[sr * BFSTR + sk], bp);
        cp16(&Bs[sr * BFSTR + sk + 8], bp + 8);
    };

    float acc[4][4][4];
    #pragma unroll
    for (int mi = 0; mi < 4; mi++)
        #pragma unroll
        for (int ni = 0; ni < 4; ni++)
            #pragma unroll
            for (int r = 0; r < 4; r++) acc[mi][ni][r] = 0.f;

    const int ntiles = K >> 5;
    issue(0, 0);  cp_commit();
    issue(32, 1); cp_commit();
    issue(64, 2); cp_commit();

    for (int t = 0; t < ntiles; t++) {
        const uint32_t* Aw = W + (t & 3) * BFSTAGE;
        const uint32_t* Bw = Aw + BFTILEW;

        if (t + 2 < ntiles) cp_wait<2>();
        else if (t + 1 < ntiles) cp_wait<1>();
        else cp_wait<0>();
        __syncthreads();

        #pragma unroll
        for (int ks = 0; ks < 2; ks++) {
            uint32_t a[4][4], b[4][2];
            const int c = ks * 8 + (lane & 3);
            #pragma unroll
            for (int mi = 0; mi < 4; mi++) {
                const uint32_t* p = &Aw[(wm + mi * 16 + (lane >> 2)) * BFW + c];
                a[mi][0] = p[0];
                a[mi][1] = p[8 * BFW];
                a[mi][2] = p[4];
                a[mi][3] = p[8 * BFW + 4];
            }
            #pragma unroll
            for (int ni = 0; ni < 4; ni++) {
                const uint32_t* p = &Bw[(wn + ni * 8 + (lane >> 2)) * BFW + c];
                b[ni][0] = p[0];
                b[ni][1] = p[4];
            }
            #pragma unroll
            for (int mi = 0; mi < 4; mi++)
                #pragma unroll
                for (int ni = 0; ni < 4; ni++)
                    mma_bf16(acc[mi][ni][0], acc[mi][ni][1],
                             acc[mi][ni][2], acc[mi][ni][3],
                             a[mi][0], a[mi][1], a[mi][2], a[mi][3],
                             b[ni][0], b[ni][1]);
        }

        if (t + 3 < ntiles) {
            issue((t + 3) << 5, (t + 3) & 3);
            cp_commit();
        }
    }

    // ---- epilogue ----
    #pragma unroll
    for (int mi = 0; mi < 4; mi++) {
        int r0 = m0 + wm + mi * 16 + (lane >> 2);
        #pragma unroll
        for (int ni = 0; ni < 4; ni++) {
            int c = n0 + wn + ni * 8 + 2 * (lane & 3);
            float bx = bias[c], by = bias[c + 1];
            float v0 = acc[mi][ni][0] + bx, v1 = acc[mi][ni][1] + by;
            float v2 = acc[mi][ni][2] + bx, v3 = acc[mi][ni][3] + by;
            if (relu) {
                v0 = fmaxf(v0, 0.f); v1 = fmaxf(v1, 0.f);
                v2 = fmaxf(v2, 0.f); v3 = fmaxf(v3, 0.f);
            }
            if (OUTBF) {
                __nv_bfloat16* Ch = (__nv_bfloat16*)Call + (size_t)e * CAPN * N;
                if (r0 < mlim)
                    *(__nv_bfloat162*)(Ch + (size_t)r0 * N + c)       = __floats2bfloat162_rn(v0, v1);
                if (r0 + 8 < mlim)
                    *(__nv_bfloat162*)(Ch + (size_t)(r0 + 8) * N + c) = __floats2bfloat162_rn(v2, v3);
            } else {
                float* Cf = (float*)Call + (size_t)e * CAPN * N;
                if (r0 < mlim)     *(float2*)(Cf + (size_t)r0 * N + c)       = make_float2(v0, v1);
                if (r0 + 8 < mlim) *(float2*)(Cf + (size_t)(r0 + 8) * N + c) = make_float2(v2, v3);
            }
        }
    }
}

// ======================================================================
// TF32 tensor-core flash attention (unchanged — keeps x bitwise stable).
// ======================================================================
#define ABR 128
#define ABC 32

__global__ __launch_bounds__(256) void attn_mma(
    const float* __restrict__ qkv, float* __restrict__ ctx)
{
    __shared__ float Ks[ABC][68];
    __shared__ float Vs[ABC][68];
    __shared__ float Ps[ABR][40];

    const int bh = blockIdx.y;
    const int b = bh / HH, h = bh % HH;
    const int q0 = blockIdx.x * ABR;
    const int tid = threadIdx.x, lane = tid & 31, warp = tid >> 5;
    const int wm = warp * 16;

    uint32_t qa[8][4];
    {
        int ra = q0 + wm + (lane >> 2);
        int rb = ra + 8;
        const float* pa = qkv + ((size_t)ra * BB + b) * (3 * DD) + h * DHH;
        const float* pb = qkv + ((size_t)rb * BB + b) * (3 * DD) + h * DHH;
        #pragma unroll
        for (int kk = 0; kk < 8; kk++) {
            int c = kk * 8 + (lane & 3);
            qa[kk][0] = __float_as_uint(to_tf32(pa[c    ] * 0.125f));
            qa[kk][1] = __float_as_uint(to_tf32(pb[c    ] * 0.125f));
            qa[kk][2] = __float_as_uint(to_tf32(pa[c + 4] * 0.125f));
            qa[kk][3] = __float_as_uint(to_tf32(pb[c + 4] * 0.125f));
        }
    }

    float m0 = -1e30f, m1 = -1e30f, l0 = 0.f, l1 = 0.f;
    float o[8][4];
    #pragma unroll
    for (int ni = 0; ni < 8; ni++)
        #pragma unroll
        for (int r = 0; r < 4; r++) o[ni][r] = 0.f;

    const int lr = tid >> 3;
    const int lc = (tid & 7) * 8;
    const int pra = wm + (lane >> 2);
    const int prb = pra + 8;
    const int pc  = 2 * (lane & 3);

    for (int kt = 0; kt < SS; kt += ABC) {
        const float* kr = qkv + ((size_t)(kt + lr) * BB + b) * (3 * DD) + DD + h * DHH + lc;
        float4 k1 = *(const float4*)(kr);
        float4 k2 = *(const float4*)(kr + 4);
        float4 v1 = *(const float4*)(kr + DD);
        float4 v2 = *(const float4*)(kr + DD + 4);
        Ks[lr][lc+0] = to_tf32(k1.x); Ks[lr][lc+1] = to_tf32(k1.y);
        Ks[lr][lc+2] = to_tf32(k1.z); Ks[lr][lc+3] = to_tf32(k1.w);
        Ks[lr][lc+4] = to_tf32(k2.x); Ks[lr][lc+5] = to_tf32(k2.y);
        Ks[lr][lc+6] = to_tf32(k2.z); Ks[lr][lc+7] = to_tf32(k2.w);
        Vs[lr][lc+0] = to_tf32(v1.x); Vs[lr][lc+1] = to_tf32(v1.y);
        Vs[lr][lc+2] = to_tf32(v1.z); Vs[lr][lc+3] = to_tf32(v1.w);
        Vs[lr][lc+4] = to_tf32(v2.x); Vs[lr][lc+5] = to_tf32(v2.y);
        Vs[lr][lc+6] = to_tf32(v2.z); Vs[lr][lc+7] = to_tf32(v2.w);
        __syncthreads();

        float s[4][4];
        #pragma unroll
        for (int ni = 0; ni < 4; ni++)
            #pragma unroll
            for (int r = 0; r < 4; r++) s[ni][r] = 0.f;

        #pragma unroll
        for (int kk = 0; kk < 8; kk++) {
            uint32_t kb[4][2];
            #pragma unroll
            for (int ni = 0; ni < 4; ni++) {
                kb[ni][0] = __float_as_uint(Ks[ni*8 + (lane>>2)][kk*8 + (lane&3)    ]);
                kb[ni][1] = __float_as_uint(Ks[ni*8 + (lane>>2)][kk*8 + (lane&3) + 4]);
            }
            #pragma unroll
            for (int ni = 0; ni < 4; ni++)
                mma_tf32(s[ni][0], s[ni][1], s[ni][2], s[ni][3],
                         qa[kk][0], qa[kk][1], qa[kk][2], qa[kk][3],
                         kb[ni][0], kb[ni][1]);
        }

        float mt0 = -1e30f, mt1 = -1e30f;
        #pragma unroll
        for (int ni = 0; ni < 4; ni++) {
            mt0 = fmaxf(mt0, fmaxf(s[ni][0], s[ni][1]));
            mt1 = fmaxf(mt1, fmaxf(s[ni][2], s[ni][3]));
        }
        mt0 = fmaxf(mt0, __shfl_xor_sync(0xffffffffu, mt0, 1));
        mt0 = fmaxf(mt0, __shfl_xor_sync(0xffffffffu, mt0, 2));
        mt1 = fmaxf(mt1, __shfl_xor_sync(0xffffffffu, mt1, 1));
        mt1 = fmaxf(mt1, __shfl_xor_sync(0xffffffffu, mt1, 2));
        float mn0 = fmaxf(m0, mt0), mn1 = fmaxf(m1, mt1);
        float f0 = __expf(m0 - mn0), f1 = __expf(m1 - mn1);
        m0 = mn0; m1 = mn1;
        l0 *= f0; l1 *= f1;
        #pragma unroll
        for (int ni = 0; ni < 8; ni++) {
            o[ni][0] *= f0; o[ni][1] *= f0;
            o[ni][2] *= f1; o[ni][3] *= f1;
        }

        float rs0 = 0.f, rs1 = 0.f;
        #pragma unroll
        for (int ni = 0; ni < 4; ni++) {
            float p00 = __expf(s[ni][0] - m0);
            float p01 = __expf(s[ni][1] - m0);
            float p10 = __expf(s[ni][2] - m1);
            float p11 = __expf(s[ni][3] - m1);
            rs0 += p00 + p01; rs1 += p10 + p11;
            Ps[pra][ni*8 + pc    ] = p00;
            Ps[pra][ni*8 + pc + 1] = p01;
            Ps[prb][ni*8 + pc    ] = p10;
            Ps[prb][ni*8 + pc + 1] = p11;
        }
        rs0 += __shfl_xor_sync(0xffffffffu, rs0, 1);
        rs0 += __shfl_xor_sync(0xffffffffu, rs0, 2);
        rs1 += __shfl_xor_sync(0xffffffffu, rs1, 1);
        rs1 += __shfl_xor_sync(0xffffffffu, rs1, 2);
        l0 += rs0; l1 += rs1;

        __syncwarp();

        #pragma unroll
        for (int kk = 0; kk < 4; kk++) {
            uint32_t pfa[4];
            pfa[0] = __float_as_uint(to_tf32(Ps[pra][kk*8 + (lane&3)    ]));
            pfa[1] = __float_as_uint(to_tf32(Ps[prb][kk*8 + (lane&3)    ]));
            pfa[2] = __float_as_uint(to_tf32(Ps[pra][kk*8 + (lane&3) + 4]));
            pfa[3] = __float_as_uint(to_tf32(Ps[prb][kk*8 + (lane&3) + 4]));
            #pragma unroll
            for (int ni = 0; ni < 8; ni++) {
                uint32_t vb0 = __float_as_uint(Vs[kk*8 + (lane&3)    ][ni*8 + (lane>>2)]);
                uint32_t vb1 = __float_as_uint(Vs[kk*8 + (lane&3) + 4][ni*8 + (lane>>2)]);
                mma_tf32(o[ni][0], o[ni][1], o[ni][2], o[ni][3],
                         pfa[0], pfa[1], pfa[2], pfa[3], vb0, vb1);
            }
        }
        __syncthreads();
    }

    float i0 = 1.f / l0, i1 = 1.f / l1;
    int ra = q0 + wm + (lane >> 2), rb = ra + 8;
    float* ca = ctx + ((size_t)ra * BB + b) * DD + h * DHH;
    float* cb = ctx + ((size_t)rb * BB + b) * DD + h * DHH;
    #pragma unroll
    for (int ni = 0; ni < 8; ni++) {
        int c = ni * 8 + pc;
        *(float2*)(ca + c) = make_float2(o[ni][0] * i0, o[ni][1] * i0);
        *(float2*)(cb + c) = make_float2(o[ni][2] * i1, o[ni][3] * i1);
    }
}

// ---------------- out = LayerNorm(a + b) ----------------
__global__ __launch_bounds__(256) void add_ln_kernel(
    const float* __restrict__ a, const float* __restrict__ bvec,
    const float* __restrict__ g, const float* __restrict__ beta,
    float* __restrict__ out)
{
    int t = blockIdx.x;
    __shared__ float row[DD];
    __shared__ float red[256];
    int tid = threadIdx.x;
    float s = 0.f;
    for (int d = tid; d < DD; d += 256) {
        float v = a[(size_t)t * DD + d] + bvec[(size_t)t * DD + d];
        row[d] = v; s += v;
    }
    red[tid] = s; __syncthreads();
    for (int o = 128; o > 0; o >>= 1) { if (tid < o) red[tid] += red[tid + o]; __syncthreads(); }
    float mean = red[0] * (1.f / DD);
    __syncthreads();
    float vs = 0.f;
    for (int d = tid; d < DD; d += 256) { float dv = row[d] - mean; vs += dv * dv; }
    red[tid] = vs; __syncthreads();
    for (int o = 128; o > 0; o >>= 1) { if (tid < o) red[tid] += red[tid + o]; __syncthreads(); }
    float rstd = rsqrtf(red[0] * (1.f / DD) + 1e-5f);
    for (int d = tid; d < DD; d += 256)
        out[(size_t)t * DD + d] = (row[d] - mean) * rstd * g[d] + beta[d];
}

// ---------------- router: warp per token ----------------
__global__ __launch_bounds__(256) void router_kernel(
    const float* __restrict__ x, const float* __restrict__ rw,
    const float* __restrict__ rb)
{
    int warp = threadIdx.x >> 5, lane = threadIdx.x & 31;
    int t = blockIdx.x * 8 + warp;
    __shared__ float sprob[EE];
    if (threadIdx.x < EE) sprob[threadIdx.x] = 0.f;
    __syncthreads();

    float pe[EE];
    #pragma unroll
    for (int e = 0; e < EE; e++) pe[e] = 0.f;
    const float* xr = x + (size_t)t * DD;
    for (int d = lane; d < DD; d += 32) {
        float xv = xr[d];
        #pragma unroll
        for (int e = 0; e < EE; e++) pe[e] += xv * rw[e * DD + d];
    }
    #pragma unroll
    for (int e = 0; e < EE; e++)
        #pragma unroll
        for (int o = 16; o > 0; o >>= 1) pe[e] += __shfl_xor_sync(0xffffffffu, pe[e], o);

    if (lane == 0) {
        float mx = -1e30f;
        #pragma unroll
        for (int e = 0; e < EE; e++) { pe[e] += rb[e]; mx = fmaxf(mx, pe[e]); }
        float p[EE]; float sum = 0.f;
        #pragma unroll
        for (int e = 0; e < EE; e++) { p[e] = __expf(pe[e] - mx); sum += p[e]; }
        float inv = 1.f / sum;
        int best = 0; float bp = -1.f;
        #pragma unroll
        for (int e = 0; e < EE; e++) { p[e] *= inv; }
        #pragma unroll
        for (int e = 0; e < EE; e++) { if (p[e] > bp) { bp = p[e]; best = e; } }
        g_eidx[t] = best; g_gate[t] = bp;
        #pragma unroll
        for (int e = 0; e < EE; e++) atomicAdd(&sprob[e], p[e]);
    }
    __syncthreads();
    if (threadIdx.x < EE) atomicAdd(&g_probsum[threadIdx.x], sprob[threadIdx.x]);
}

// ---------------- per-expert queue positions ----------------
__global__ void pos_kernel() {
    int warp = threadIdx.x >> 5, lane = threadIdx.x & 31;
    if (warp >= EE) return;
    int base = 0;
    for (int t0 = 0; t0 < TT; t0 += 32) {
        int t = t0 + lane;
        bool m = (g_eidx[t] == warp);
        unsigned msk = __ballot_sync(0xffffffffu, m);
        if (m) g_pos[t] = base + __popc(msk & ((1u << lane) - 1u));
        base += __popc(msk);
    }
    if (lane == 0) {
        g_cntfull[warp] = base;
        g_cnt[warp] = base < CAPN ? base : CAPN;
    }
}

// ---------------- gather tokens into expert buffers (bf16) ----------------
__global__ __launch_bounds__(192) void gather_kernel(const float* __restrict__ x) {
    int t = blockIdx.x;
    int p = g_pos[t];
    if (p >= CAPN) return;
    int e = g_eidx[t];
    __nv_bfloat16* dst = g_bufb + ((size_t)e * CAPN + p) * DD + threadIdx.x * 4;
    const float4 v = ((const float4*)(x + (size_t)t * DD))[threadIdx.x];
    *(__nv_bfloat162*)(dst)     = __floats2bfloat162_rn(v.x, v.y);
    *(__nv_bfloat162*)(dst + 2) = __floats2bfloat162_rn(v.z, v.w);
}

// ---------------- final: out = LN(x + gate * y[eidx,pos]) ----------------
__global__ __launch_bounds__(256) void final_kernel(
    const float* __restrict__ x, const float* __restrict__ g,
    const float* __restrict__ beta, float* __restrict__ out)
{
    int t = blockIdx.x;
    __shared__ float row[DD];
    __shared__ float red[256];
    int tid = threadIdx.x;
    int p = g_pos[t], e = g_eidx[t];
    float ga = g_gate[t];
    bool keep = (p < CAPN);
    const float* yrow = g_y + ((size_t)e * CAPN + (keep ? p : 0)) * DD;

    float s = 0.f;
    for (int d = tid; d < DD; d += 256) {
        float v = x[(size_t)t * DD + d] + (keep ? ga * yrow[d] : 0.f);
        row[d] = v; s += v;
    }
    red[tid] = s; __syncthreads();
    for (int o = 128; o > 0; o >>= 1) { if (tid < o) red[tid] += red[tid + o]; __syncthreads(); }
    float mean = red[0] * (1.f / DD);
    __syncthreads();
    float vs = 0.f;
    for (int d = tid; d < DD; d += 256) { float dv = row[d] - mean; vs += dv * dv; }
    red[tid] = vs; __syncthreads();
    for (int o = 128; o > 0; o >>= 1) { if (tid < o) red[tid] += red[tid + o]; __syncthreads(); }
    float rstd = rsqrtf(red[0] * (1.f / DD) + 1e-5f);
    for (int d = tid; d < DD; d += 256)
        out[(size_t)t * DD + d] = (row[d] - mean) * rstd * g[d] + beta[d];
}

// ---------------- lb loss ----------------
__global__ void loss_kernel(float* __restrict__ out) {
    float acc = 0.f;
    for (int e = 0; e < EE; e++)
        acc += ((float)g_cntfull[e] / (float)TT) * (g_probsum[e] / (float)TT);
    out[(size_t)TT * DD] = (float)EE * acc;
}

// ---------------- launch ----------------
extern "C" void kernel_launch(void* const* d_in, const int* in_sizes, int n_in,
                              void* d_out, int out_size)
{
    const float* src   = (const float*)d_in[0];
    const float* inw   = (const float*)d_in[1];
    const float* inb   = (const float*)d_in[2];
    const float* outw  = (const float*)d_in[3];
    const float* outb  = (const float*)d_in[4];
    const float* n1g   = (const float*)d_in[5];
    const float* n1b   = (const float*)d_in[6];
    const float* rw    = (const float*)d_in[7];
    const float* rb    = (const float*)d_in[8];
    const float* w1    = (const float*)d_in[9];
    const float* b1    = (const float*)d_in[10];
    const float* w2    = (const float*)d_in[11];
    const float* b2    = (const float*)d_in[12];
    const float* n2g   = (const float*)d_in[13];
    const float* n2b   = (const float*)d_in[14];
    float* out = (float*)d_out;

    float *p_qkv, *p_ctx, *p_attn, *p_x, *p_y;
    __nv_bfloat16 *p_bufb, *p_hb, *p_w1b, *p_w2b;
    cudaGetSymbolAddress((void**)&p_qkv,  g_qkv);
    cudaGetSymbolAddress((void**)&p_ctx,  g_ctx);
    cudaGetSymbolAddress((void**)&p_attn, g_attn);
    cudaGetSymbolAddress((void**)&p_x,    g_x);
    cudaGetSymbolAddress((void**)&p_y,    g_y);
    cudaGetSymbolAddress((void**)&p_bufb, g_bufb);
    cudaGetSymbolAddress((void**)&p_hb,   g_hb);
    cudaGetSymbolAddress((void**)&p_w1b,  g_w1b);
    cudaGetSymbolAddress((void**)&p_w2b,  g_w2b);

    const int smem_tf = 3 * TSTAGE * 4;          // 110592 B
    const int smem_bf = 4 * BFSTAGE * 4;         // 81920 B
    cudaFuncSetAttribute(gemm_tf32_bt,
                         cudaFuncAttributeMaxDynamicSharedMemorySize, smem_tf);
    cudaFuncSetAttribute(gemm_bf16_moe<true>,
                         cudaFuncAttributeMaxDynamicSharedMemorySize, smem_bf);
    cudaFuncSetAttribute(gemm_bf16_moe<false>,
                         cudaFuncAttributeMaxDynamicSharedMemorySize, smem_bf);

    zero_kernel<<<1, 32>>>();

    // weight convert+transpose: w1[e][D][F]->[e][F][D], w2[e][F][D]->[e][D][F]
    convert_t<<<dim3(FF / 32, DD / 32, EE), dim3(32, 8)>>>(w1, p_w1b, DD, FF);
    convert_t<<<dim3(DD / 32, FF / 32, EE), dim3(32, 8)>>>(w2, p_w2b, FF, DD);

    // QKV = src @ in_proj_w^T + b   (tf32, bitwise-stable)
    gemm_tf32_bt<<<dim3((3 * DD) / 128, TT / 128), 256, smem_tf>>>(
        src, inw, inb, p_qkv, DD, 3 * DD);

    // attention -> ctx
    attn_mma<<<dim3(SS / ABR, BB * HH), 256>>>(p_qkv, p_ctx);

    // attn_out = ctx @ out_proj_w^T + b
    gemm_tf32_bt<<<dim3(DD / 128, TT / 128), 256, smem_tf>>>(
        p_ctx, outw, outb, p_attn, DD, DD);

    // x = LN(src + attn_out)
    add_ln_kernel<<<TT, 256>>>(src, p_attn, n1g, n1b, p_x);

    // routing
    router_kernel<<<TT / 8, 256>>>(p_x, rw, rb);
    pos_kernel<<<1, 256>>>();
    gather_kernel<<<TT, 192>>>(p_x);

    // expert FFN (bf16 tensor cores)
    gemm_bf16_moe<true><<<dim3(FF / 128, CAPN / 128, EE), 256, smem_bf>>>(
        p_bufb, p_w1b, b1, p_hb, DD, FF, 1);
    gemm_bf16_moe<false><<<dim3(DD / 128, CAPN / 128, EE), 256, smem_bf>>>(
        p_hb, p_w2b, b2, p_y, FF, DD, 0);

    // out = LN(x + gate*moe)
    final_kernel<<<TT, 256>>>(p_x, n2g, n2b, out);
    loss_kernel<<<1, 1>>>(out);
}